// round 1
// baseline (speedup 1.0000x reference)
#include <cuda_runtime.h>

#define Dm 128
#define NH 8
#define NNODE 40000
#define NEDGE 640000

// ---------------- scratch (static device globals; no runtime allocation) ----
__device__ float g_h[(size_t)NNODE * Dm];
__device__ float g_q[(size_t)NNODE * Dm];
__device__ float g_W0[(size_t)NEDGE * Dm];   // linear filter branch
__device__ float g_u[(size_t)NEDGE * Dm];    // ssp(f@W_r1+b)
__device__ float g_m[(size_t)NEDGE * Dm];    // filtered messages
__device__ float g_k[(size_t)NEDGE * Dm];
__device__ float g_v[(size_t)NEDGE * Dm];
__device__ float g_sc[(size_t)NEDGE * NH];   // scores, then exp values (in-place)
__device__ unsigned g_smax[(size_t)NNODE * NH];
__device__ float g_den[(size_t)NNODE * NH];
__device__ float g_agg[(size_t)NNODE * Dm];

// ---------------- helpers ----------------------------------------------------
__device__ __forceinline__ unsigned fenc(float f) {
    unsigned u = __float_as_uint(f);
    return (u & 0x80000000u) ? ~u : (u | 0x80000000u);
}
__device__ __forceinline__ float fdec(unsigned u) {
    return __uint_as_float((u & 0x80000000u) ? (u ^ 0x80000000u) : ~u);
}
#define SMAX_INIT 0x007fffffu   // fenc(-inf)

__device__ __forceinline__ float sspf(float v) {
    // softplus(v) - ln2
    float sp = (v > 20.f) ? v : log1pf(expf(v));
    return sp - 0.6931471805599453f;
}
__device__ __forceinline__ float cutoff(float r) {
    // 0.5*(cos(pi*r/8)+1) * (r<8)
    float c = 0.5f * (cosf(r * 0.39269908169872414f) + 1.f);
    return (r < 8.f) ? c : 0.f;
}

// ---------------- init -------------------------------------------------------
__global__ void init_kernel() {
    int gid = blockIdx.x * blockDim.x + threadIdx.x;
    if (gid < NNODE * Dm) g_agg[gid] = 0.f;
    if (gid < NNODE * NH) { g_den[gid] = 0.f; g_smax[gid] = SMAX_INIT; }
}

__global__ void add_h_kernel(const float* __restrict__ x, const float* __restrict__ t) {
    int gid = blockIdx.x * blockDim.x + threadIdx.x;
    if (gid < NNODE * Dm) g_h[gid] = x[gid] + t[gid];
}

// ---------------- tiled fp32 GEMM: C[M,128] = A[M,K] @ B[K,128] + epilogue ---
// MODE 0: out = acc + bias
// MODE 1: out = ssp(acc + bias)
// MODE 2: w = acc + bias + aux0[row];  out = aux1[src[row]] * w * cutoff(r_ij[row])
// MODE 3: v = acc + bias + aux0[row];  out = LayerNorm_row(v)*ln_g + ln_b
template <int MODE>
__global__ __launch_bounds__(256, 2)
void gemm128(const float* __restrict__ A, const float* __restrict__ B,
             const float* __restrict__ bias, float* __restrict__ Cout,
             int M, int K,
             const float* __restrict__ aux0, const float* __restrict__ aux1,
             const float* __restrict__ r_ij, const int* __restrict__ srcidx,
             const float* __restrict__ ln_g, const float* __restrict__ ln_b)
{
    __shared__ float As[16][128];
    __shared__ float Bs[16][128];

    const int tid = threadIdx.x;
    const int ty = tid >> 4;        // 0..15
    const int tx = tid & 15;        // 0..15
    const int rowBase = blockIdx.x * 128;

    float acc[8][8];
#pragma unroll
    for (int i = 0; i < 8; ++i)
#pragma unroll
        for (int j = 0; j < 8; ++j) acc[i][j] = 0.f;

    for (int k0 = 0; k0 < K; k0 += 16) {
        // --- load A tile: 128 rows x 16 cols (transposed into As[k][row]) ---
#pragma unroll
        for (int p = 0; p < 2; ++p) {
            int r = p * 64 + (tid >> 2);
            int c = (tid & 3) * 4;
            int gr = rowBase + r;
            float4 av = make_float4(0.f, 0.f, 0.f, 0.f);
            if (gr < M) av = *(const float4*)(A + (size_t)gr * K + k0 + c);
            As[c + 0][r] = av.x; As[c + 1][r] = av.y;
            As[c + 2][r] = av.z; As[c + 3][r] = av.w;
        }
        // --- load B tile: 16 rows x 128 cols ---
#pragma unroll
        for (int p = 0; p < 2; ++p) {
            int r = p * 8 + (tid >> 5);
            int c = (tid & 31) * 4;
            float4 bv = *(const float4*)(B + (size_t)(k0 + r) * 128 + c);
            *(float4*)&Bs[r][c] = bv;
        }
        __syncthreads();

#pragma unroll
        for (int k = 0; k < 16; ++k) {
            float a[8], b[8];
            *(float4*)(a)     = *(const float4*)&As[k][ty * 4];
            *(float4*)(a + 4) = *(const float4*)&As[k][64 + ty * 4];
            *(float4*)(b)     = *(const float4*)&Bs[k][tx * 4];
            *(float4*)(b + 4) = *(const float4*)&Bs[k][64 + tx * 4];
#pragma unroll
            for (int i = 0; i < 8; ++i)
#pragma unroll
                for (int j = 0; j < 8; ++j) acc[i][j] += a[i] * b[j];
        }
        __syncthreads();
    }

    // row-local indices for micro-tile
    int rloc[8];
#pragma unroll
    for (int i = 0; i < 8; ++i) rloc[i] = (i < 4) ? (ty * 4 + i) : (64 + ty * 4 + (i - 4));

    if constexpr (MODE == 3) {
        __shared__ float rs[128], rq[128];
        if (tid < 128) { rs[tid] = 0.f; rq[tid] = 0.f; }
        __syncthreads();
#pragma unroll
        for (int i = 0; i < 8; ++i) {
            int rl = rloc[i];
            int row = rowBase + rl;
            if (row < M) {
                float s = 0.f, q2 = 0.f;
#pragma unroll
                for (int jj = 0; jj < 2; ++jj)
#pragma unroll
                    for (int j0 = 0; j0 < 4; ++j0) {
                        int col = jj * 64 + tx * 4 + j0;
                        float v = acc[i][jj * 4 + j0] + bias[col] + aux0[(size_t)row * 128 + col];
                        acc[i][jj * 4 + j0] = v;
                        s += v; q2 += v * v;
                    }
                atomicAdd(&rs[rl], s);
                atomicAdd(&rq[rl], q2);
            }
        }
        __syncthreads();
#pragma unroll
        for (int i = 0; i < 8; ++i) {
            int rl = rloc[i];
            int row = rowBase + rl;
            if (row < M) {
                float mean = rs[rl] * (1.f / 128.f);
                float var = rq[rl] * (1.f / 128.f) - mean * mean;
                float inv = rsqrtf(var + 1e-5f);
#pragma unroll
                for (int jj = 0; jj < 2; ++jj) {
                    int cb = jj * 64 + tx * 4;
                    float4 o;
                    o.x = (acc[i][jj * 4 + 0] - mean) * inv * ln_g[cb + 0] + ln_b[cb + 0];
                    o.y = (acc[i][jj * 4 + 1] - mean) * inv * ln_g[cb + 1] + ln_b[cb + 1];
                    o.z = (acc[i][jj * 4 + 2] - mean) * inv * ln_g[cb + 2] + ln_b[cb + 2];
                    o.w = (acc[i][jj * 4 + 3] - mean) * inv * ln_g[cb + 3] + ln_b[cb + 3];
                    *(float4*)(Cout + (size_t)row * 128 + cb) = o;
                }
            }
        }
    } else {
#pragma unroll
        for (int i = 0; i < 8; ++i) {
            int row = rowBase + rloc[i];
            if (row >= M) continue;
            float Ce = 0.f; const float* hrow = nullptr;
            if constexpr (MODE == 2) {
                Ce = cutoff(r_ij[row]);
                hrow = aux1 + (size_t)srcidx[row] * 128;
            }
#pragma unroll
            for (int jj = 0; jj < 2; ++jj) {
                int cb = jj * 64 + tx * 4;
                float4 o;
#pragma unroll
                for (int j0 = 0; j0 < 4; ++j0) {
                    int col = cb + j0;
                    float v = acc[i][jj * 4 + j0] + bias[col];
                    if constexpr (MODE == 1) v = sspf(v);
                    if constexpr (MODE == 2) {
                        v = v + aux0[(size_t)row * 128 + col];
                        v = hrow[col] * v * Ce;
                    }
                    ((float*)&o)[j0] = v;
                }
                *(float4*)(Cout + (size_t)row * 128 + cb) = o;
            }
        }
    }
}

// ---------------- scores + segment max ---------------------------------------
__global__ void score_kernel(const int* __restrict__ dst) {
    int gid = blockIdx.x * blockDim.x + threadIdx.x;
    if (gid >= NEDGE * NH) return;
    int e = gid >> 3, h = gid & 7;
    int d = dst[e];
    const float4* kp = (const float4*)(g_k + (size_t)e * 128 + h * 16);
    const float4* qp = (const float4*)(g_q + (size_t)d * 128 + h * 16);
    float s = 0.f;
#pragma unroll
    for (int i = 0; i < 4; ++i) {
        float4 kv = kp[i], qv = qp[i];
        s += kv.x * qv.x + kv.y * qv.y + kv.z * qv.z + kv.w * qv.w;
    }
    s *= 0.25f;   // / sqrt(16)
    g_sc[gid] = s;
    atomicMax(&g_smax[d * NH + h], fenc(s));
}

// ---------------- exp + segment sum ------------------------------------------
__global__ void expsum_kernel(const int* __restrict__ dst) {
    int gid = blockIdx.x * blockDim.x + threadIdx.x;
    if (gid >= NEDGE * NH) return;
    int e = gid >> 3, h = gid & 7;
    int d = dst[e];
    float mx = fdec(g_smax[d * NH + h]);
    float ex = expf(g_sc[gid] - mx);
    g_sc[gid] = ex;
    atomicAdd(&g_den[d * NH + h], ex);
}

// ---------------- weighted scatter of v --------------------------------------
__global__ void scatter_kernel(const int* __restrict__ dst) {
    int gid = blockIdx.x * blockDim.x + threadIdx.x;
    if (gid >= NEDGE * 32) return;
    int e = gid >> 5, t = gid & 31;
    int d0 = t * 4;
    int h = d0 >> 4;
    int d = dst[e];
    float alpha = g_sc[e * NH + h] / (g_den[d * NH + h] + 1e-16f);
    float4 vv = *(const float4*)(g_v + (size_t)e * 128 + d0);
    float* ap = g_agg + (size_t)d * 128 + d0;
    atomicAdd(ap + 0, alpha * vv.x);
    atomicAdd(ap + 1, alpha * vv.y);
    atomicAdd(ap + 2, alpha * vv.z);
    atomicAdd(ap + 3, alpha * vv.w);
}

// ---------------- launch ------------------------------------------------------
extern "C" void kernel_launch(void* const* d_in, const int* in_sizes, int n_in,
                              void* d_out, int out_size) {
    const float* x     = (const float*)d_in[0];
    const float* t     = (const float*)d_in[1];
    const float* f_ij  = (const float*)d_in[2];
    const float* r_ij  = (const float*)d_in[3];
    const int*   src   = (const int*)d_in[4];
    const int*   dst   = (const int*)d_in[5];
    const float* W_lin = (const float*)d_in[6];
    const float* b_lin = (const float*)d_in[7];
    const float* W_r1  = (const float*)d_in[8];
    const float* b_r1  = (const float*)d_in[9];
    const float* W_r2  = (const float*)d_in[10];
    const float* b_r2  = (const float*)d_in[11];
    const float* Wq    = (const float*)d_in[12];
    const float* bq    = (const float*)d_in[13];
    const float* Wk    = (const float*)d_in[14];
    const float* bk    = (const float*)d_in[15];
    const float* Wv    = (const float*)d_in[16];
    const float* bv    = (const float*)d_in[17];
    const float* Wo    = (const float*)d_in[18];
    const float* bo    = (const float*)d_in[19];
    const float* ln_g  = (const float*)d_in[20];
    const float* ln_b  = (const float*)d_in[21];
    float* out = (float*)d_out;

    float *ph, *pq, *pW0, *pu, *pm, *pk, *pv;
    cudaGetSymbolAddress((void**)&ph,  g_h);
    cudaGetSymbolAddress((void**)&pq,  g_q);
    cudaGetSymbolAddress((void**)&pW0, g_W0);
    cudaGetSymbolAddress((void**)&pu,  g_u);
    cudaGetSymbolAddress((void**)&pm,  g_m);
    cudaGetSymbolAddress((void**)&pk,  g_k);
    cudaGetSymbolAddress((void**)&pv,  g_v);

    const int TB = 256;
    int gridN  = (NNODE * Dm + TB - 1) / TB;       // 20000
    int gridE8 = (NEDGE * NH + TB - 1) / TB;       // 20000
    int gridE32 = (NEDGE * 32 + TB - 1) / TB;      // 80000
    int gemmE = (NEDGE + 127) / 128;               // 5000
    int gemmN = (NNODE + 127) / 128;               // 313

    init_kernel<<<gridN, TB>>>();
    add_h_kernel<<<gridN, TB>>>(x, t);

    // q = h @ Wq + bq
    gemm128<0><<<gemmN, TB>>>(ph, Wq, bq, pq, NNODE, 128,
                              nullptr, nullptr, nullptr, nullptr, nullptr, nullptr);
    // W0 = f @ W_lin + b_lin
    gemm128<0><<<gemmE, TB>>>(f_ij, W_lin, b_lin, pW0, NEDGE, 64,
                              nullptr, nullptr, nullptr, nullptr, nullptr, nullptr);
    // u = ssp(f @ W_r1 + b_r1)
    gemm128<1><<<gemmE, TB>>>(f_ij, W_r1, b_r1, pu, NEDGE, 64,
                              nullptr, nullptr, nullptr, nullptr, nullptr, nullptr);
    // m = h[src] * (u @ W_r2 + b_r2 + W0) * cutoff(r)
    gemm128<2><<<gemmE, TB>>>(pu, W_r2, b_r2, pm, NEDGE, 128,
                              pW0, ph, r_ij, src, nullptr, nullptr);
    // k = m @ Wk + bk ; v = m @ Wv + bv
    gemm128<0><<<gemmE, TB>>>(pm, Wk, bk, pk, NEDGE, 128,
                              nullptr, nullptr, nullptr, nullptr, nullptr, nullptr);
    gemm128<0><<<gemmE, TB>>>(pm, Wv, bv, pv, NEDGE, 128,
                              nullptr, nullptr, nullptr, nullptr, nullptr, nullptr);

    score_kernel<<<gridE8, TB>>>(dst);
    expsum_kernel<<<gridE8, TB>>>(dst);
    scatter_kernel<<<gridE32, TB>>>(dst);

    // out = LN(x + agg @ Wo + bo)
    float* pagg;
    cudaGetSymbolAddress((void**)&pagg, g_agg);
    gemm128<3><<<gemmN, TB>>>(pagg, Wo, bo, out, NNODE, 128,
                              x, nullptr, nullptr, nullptr, ln_g, ln_b);
}

// round 3
// speedup vs baseline: 1.0265x; 1.0265x over previous
#include <cuda_runtime.h>
#include <mma.h>
using namespace nvcuda;

#define Dm 128
#define NH 8
#define NNODE 40000
#define NEDGE 640000

// ---------------- scratch (static device globals; no runtime allocation) ----
__device__ float g_h[(size_t)NNODE * Dm];
__device__ float g_q[(size_t)NNODE * Dm];
__device__ float g_m[(size_t)NEDGE * Dm];    // filtered messages
__device__ float g_k[(size_t)NEDGE * Dm];
__device__ float g_v[(size_t)NEDGE * Dm];
__device__ float g_sc[(size_t)NEDGE * NH];   // scores, then exp values (in-place)
__device__ unsigned g_smax[(size_t)NNODE * NH];
__device__ float g_den[(size_t)NNODE * NH];
__device__ float g_agg[(size_t)NNODE * Dm];

// ---------------- helpers ----------------------------------------------------
__device__ __forceinline__ unsigned fenc(float f) {
    unsigned u = __float_as_uint(f);
    return (u & 0x80000000u) ? ~u : (u | 0x80000000u);
}
__device__ __forceinline__ float fdec(unsigned u) {
    return __uint_as_float((u & 0x80000000u) ? (u ^ 0x80000000u) : ~u);
}
#define SMAX_INIT 0x007fffffu   // fenc(-inf)

__device__ __forceinline__ float sspf(float v) {
    float sp = (v > 20.f) ? v : log1pf(expf(v));
    return sp - 0.6931471805599453f;
}
__device__ __forceinline__ float cutoff(float r) {
    float c = 0.5f * (cosf(r * 0.39269908169872414f) + 1.f);
    return (r < 8.f) ? c : 0.f;
}

// ---------------- wmma tf32 machinery ----------------------------------------
typedef wmma::fragment<wmma::matrix_a, 16, 16, 8, wmma::precision::tf32, wmma::row_major> FragA;
typedef wmma::fragment<wmma::matrix_b, 16, 16, 8, wmma::precision::tf32, wmma::row_major> FragB;
typedef wmma::fragment<wmma::accumulator, 16, 16, 8, float> FragC;

template <class F>
__device__ __forceinline__ void to_tf32(F& f) {
#pragma unroll
    for (int i = 0; i < f.num_elements; ++i) f.x[i] = wmma::__float_to_tf32(f.x[i]);
}

// one 32-deep K panel: acc[2][4] covers warp tile 32 rows x 64 cols
// warps laid out 4 (row) x 2 (col) over a 128x128 CTA tile.
__device__ __forceinline__ void mma_panel(const float* As, int lda,
                                          const float* Bs, int ldb,
                                          FragC (&acc)[2][4], int wr, int wc) {
#pragma unroll
    for (int kk = 0; kk < 4; ++kk) {
        FragA a[2]; FragB b[4];
#pragma unroll
        for (int i = 0; i < 2; ++i) {
            wmma::load_matrix_sync(a[i], As + (size_t)(wr * 32 + i * 16) * lda + kk * 8, lda);
            to_tf32(a[i]);
        }
#pragma unroll
        for (int j = 0; j < 4; ++j) {
            wmma::load_matrix_sync(b[j], Bs + (size_t)(kk * 8) * ldb + wc * 64 + j * 16, ldb);
            to_tf32(b[j]);
        }
#pragma unroll
        for (int i = 0; i < 2; ++i)
#pragma unroll
            for (int j = 0; j < 4; ++j) wmma::mma_sync(acc[i][j], a[i], b[j], acc[i][j]);
    }
}

// ---------------- init -------------------------------------------------------
__global__ void init_kernel() {
    int gid = blockIdx.x * blockDim.x + threadIdx.x;
    if (gid < NNODE * Dm) g_agg[gid] = 0.f;
    if (gid < NNODE * NH) { g_den[gid] = 0.f; g_smax[gid] = SMAX_INIT; }
}

__global__ void add_h_kernel(const float* __restrict__ x, const float* __restrict__ t) {
    int gid = blockIdx.x * blockDim.x + threadIdx.x;
    if (gid < NNODE * Dm) g_h[gid] = x[gid] + t[gid];
}

// ---------------- node GEMM (streaming A), MODE 0: +bias; MODE 3: resid+LN ---
template <int MODE>
__global__ __launch_bounds__(256)
void node_gemm(const float* __restrict__ A, const float* __restrict__ B,
               const float* __restrict__ bias, float* __restrict__ C, int M,
               const float* __restrict__ resid,
               const float* __restrict__ ln_g, const float* __restrict__ ln_b)
{
    extern __shared__ float sm[];
    const int LDA = 36, LDB = 132, LDS = 132;
    float* As = sm;                   // 128*36
    float* Bs = As + 128 * 36;        // 32*132
    float* S  = Bs + 32 * 132;        // 128*132
    const int tid = threadIdx.x, wid = tid >> 5;
    const int wr = wid >> 1, wc = wid & 1;
    const int rowBase = blockIdx.x * 128;

    FragC acc[2][4];
#pragma unroll
    for (int i = 0; i < 2; ++i)
#pragma unroll
        for (int j = 0; j < 4; ++j) wmma::fill_fragment(acc[i][j], 0.f);

    for (int k0 = 0; k0 < 128; k0 += 32) {
#pragma unroll
        for (int p = 0; p < 4; ++p) {          // A: 128x32 = 1024 float4  (FIXED: was p<2)
            int idx = tid + p * 256;
            int r = idx >> 3, cg = (idx & 7) * 4;
            float4 v = make_float4(0.f, 0.f, 0.f, 0.f);
            int gr = rowBase + r;
            if (gr < M) v = *(const float4*)(A + (size_t)gr * 128 + k0 + cg);
            *(float4*)&As[r * LDA + cg] = v;
        }
#pragma unroll
        for (int p = 0; p < 4; ++p) {          // B: 32x128 = 1024 float4
            int idx = tid + p * 256;
            int r = idx >> 5, cg = (idx & 31) * 4;
            *(float4*)&Bs[r * LDB + cg] = *(const float4*)(B + (size_t)(k0 + r) * 128 + cg);
        }
        __syncthreads();
        mma_panel(As, LDA, Bs, LDB, acc, wr, wc);
        __syncthreads();
    }

#pragma unroll
    for (int i = 0; i < 2; ++i)
#pragma unroll
        for (int j = 0; j < 4; ++j)
            wmma::store_matrix_sync(&S[(size_t)(wr * 32 + i * 16) * LDS + wc * 64 + j * 16],
                                    acc[i][j], LDS, wmma::mem_row_major);
    __syncthreads();

    if constexpr (MODE == 0) {
        for (int idx = tid; idx < 128 * 128; idx += 256) {
            int r = idx >> 7, c = idx & 127;
            int gr = rowBase + r;
            if (gr < M) C[(size_t)gr * 128 + c] = S[r * LDS + c] + bias[c];
        }
    } else {
        __shared__ float muS[128], invS[128];
        // phase A: S += bias + resid (coalesced)
        for (int idx = tid; idx < 128 * 128; idx += 256) {
            int r = idx >> 7, c = idx & 127;
            int gr = rowBase + r;
            if (gr < M) S[r * LDS + c] += bias[c] + resid[(size_t)gr * 128 + c];
        }
        __syncthreads();
        // phase B: per-row stats
        if (tid < 128) {
            int gr = rowBase + tid;
            if (gr < M) {
                float s = 0.f, q2 = 0.f;
#pragma unroll 4
                for (int c = 0; c < 128; ++c) {
                    float v = S[tid * LDS + c];
                    s += v; q2 += v * v;
                }
                float mean = s * (1.f / 128.f);
                float var = q2 * (1.f / 128.f) - mean * mean;
                muS[tid] = mean;
                invS[tid] = rsqrtf(var + 1e-5f);
            }
        }
        __syncthreads();
        for (int idx = tid; idx < 128 * 128; idx += 256) {
            int r = idx >> 7, c = idx & 127;
            int gr = rowBase + r;
            if (gr < M)
                C[(size_t)gr * 128 + c] =
                    (S[r * LDS + c] - muS[r]) * invS[r] * ln_g[c] + ln_b[c];
        }
    }
}

// ---------------- fused filter network: g_m from f_ij in one kernel ----------
// U = ssp(f@W_r1 + b_r1);  W = f@W_lin + b_lin + U@W_r2 + b_r2
// g_m = h[src] * W * cutoff(r)
__global__ __launch_bounds__(256)
void filter_kernel(const float* __restrict__ f_ij,
                   const float* __restrict__ W_r1, const float* __restrict__ b_r1,
                   const float* __restrict__ W_lin, const float* __restrict__ b_lin,
                   const float* __restrict__ W_r2, const float* __restrict__ b_r2,
                   const float* __restrict__ r_ij, const int* __restrict__ src)
{
    extern __shared__ float sm[];
    const int LDF = 68, LDU = 132, LDB = 132;
    float* Fs = sm;                 // 128*68
    float* U  = Fs + 128 * 68;      // 128*132
    float* Bs = U + 128 * 132;      // 32*132
    __shared__ float Ce[128];
    __shared__ int   srcs[128];

    const int tid = threadIdx.x, wid = tid >> 5;
    const int wr = wid >> 1, wc = wid & 1;
    const int rowBase = blockIdx.x * 128;   // NEDGE = 5000*128 exactly

    // load f tile 128x64 (2048 float4)
#pragma unroll
    for (int p = 0; p < 8; ++p) {
        int idx = tid + p * 256;
        int r = idx >> 4, cg = (idx & 15) * 4;
        *(float4*)&Fs[r * LDF + cg] = *(const float4*)(f_ij + (size_t)(rowBase + r) * 64 + cg);
    }
    if (tid < 128) {
        int e = rowBase + tid;
        Ce[tid] = cutoff(r_ij[e]);
        srcs[tid] = src[e];
    }

    FragC acc[2][4];
#pragma unroll
    for (int i = 0; i < 2; ++i)
#pragma unroll
        for (int j = 0; j < 4; ++j) wmma::fill_fragment(acc[i][j], 0.f);

    // stage 1: U = f @ W_r1   (K=64)
    for (int k0 = 0; k0 < 64; k0 += 32) {
#pragma unroll
        for (int p = 0; p < 4; ++p) {
            int idx = tid + p * 256;
            int r = idx >> 5, cg = (idx & 31) * 4;
            *(float4*)&Bs[r * LDB + cg] = *(const float4*)(W_r1 + (size_t)(k0 + r) * 128 + cg);
        }
        __syncthreads();
        mma_panel(Fs + k0, LDF, Bs, LDB, acc, wr, wc);
        __syncthreads();
    }
#pragma unroll
    for (int i = 0; i < 2; ++i)
#pragma unroll
        for (int j = 0; j < 4; ++j)
            wmma::store_matrix_sync(&U[(size_t)(wr * 32 + i * 16) * LDU + wc * 64 + j * 16],
                                    acc[i][j], LDU, wmma::mem_row_major);
    __syncthreads();
    for (int idx = tid; idx < 128 * 128; idx += 256) {
        int r = idx >> 7, c = idx & 127;
        U[r * LDU + c] = sspf(U[r * LDU + c] + b_r1[c]);
    }
    __syncthreads();

    // stage 2: acc = f@W_lin + U@W_r2
#pragma unroll
    for (int i = 0; i < 2; ++i)
#pragma unroll
        for (int j = 0; j < 4; ++j) wmma::fill_fragment(acc[i][j], 0.f);
    for (int k0 = 0; k0 < 64; k0 += 32) {
#pragma unroll
        for (int p = 0; p < 4; ++p) {
            int idx = tid + p * 256;
            int r = idx >> 5, cg = (idx & 31) * 4;
            *(float4*)&Bs[r * LDB + cg] = *(const float4*)(W_lin + (size_t)(k0 + r) * 128 + cg);
        }
        __syncthreads();
        mma_panel(Fs + k0, LDF, Bs, LDB, acc, wr, wc);
        __syncthreads();
    }
    for (int k0 = 0; k0 < 128; k0 += 32) {
#pragma unroll
        for (int p = 0; p < 4; ++p) {
            int idx = tid + p * 256;
            int r = idx >> 5, cg = (idx & 31) * 4;
            *(float4*)&Bs[r * LDB + cg] = *(const float4*)(W_r2 + (size_t)(k0 + r) * 128 + cg);
        }
        __syncthreads();
        mma_panel(U + k0, LDU, Bs, LDB, acc, wr, wc);
        __syncthreads();
    }

    // store accs into U (free now), epilogue with h-gather
#pragma unroll
    for (int i = 0; i < 2; ++i)
#pragma unroll
        for (int j = 0; j < 4; ++j)
            wmma::store_matrix_sync(&U[(size_t)(wr * 32 + i * 16) * LDU + wc * 64 + j * 16],
                                    acc[i][j], LDU, wmma::mem_row_major);
    __syncthreads();
    for (int idx = tid; idx < 128 * 128; idx += 256) {
        int r = idx >> 7, c = idx & 127;
        float w = U[r * LDU + c] + b_lin[c] + b_r2[c];
        float hv = g_h[(size_t)srcs[r] * 128 + c];
        g_m[(size_t)(rowBase + r) * 128 + c] = hv * w * Ce[r];
    }
}

// ---------------- fused k/v: load m tile once, two GEMMs ---------------------
__global__ __launch_bounds__(256)
void kv_kernel(const float* __restrict__ Wk, const float* __restrict__ bk,
               const float* __restrict__ Wv, const float* __restrict__ bv)
{
    extern __shared__ float sm[];
    const int LDA = 132, LDB = 132, LDS = 132;
    float* As = sm;                   // 128*132
    float* Bs = As + 128 * 132;       // 32*132
    float* S  = Bs + 32 * 132;        // 128*132
    const int tid = threadIdx.x, wid = tid >> 5;
    const int wr = wid >> 1, wc = wid & 1;
    const int rowBase = blockIdx.x * 128;

    // load m tile 128x128 (4096 float4)
#pragma unroll
    for (int p = 0; p < 16; ++p) {
        int idx = tid + p * 256;
        int r = idx >> 5, cg = (idx & 31) * 4;
        *(float4*)&As[r * LDA + cg] = *(const float4*)(g_m + (size_t)(rowBase + r) * 128 + cg);
    }

#pragma unroll
    for (int pass = 0; pass < 2; ++pass) {
        const float* B = pass ? Wv : Wk;
        const float* bias = pass ? bv : bk;
        float* Out = pass ? g_v : g_k;

        FragC acc[2][4];
#pragma unroll
        for (int i = 0; i < 2; ++i)
#pragma unroll
            for (int j = 0; j < 4; ++j) wmma::fill_fragment(acc[i][j], 0.f);

        for (int k0 = 0; k0 < 128; k0 += 32) {
#pragma unroll
            for (int p = 0; p < 4; ++p) {
                int idx = tid + p * 256;
                int r = idx >> 5, cg = (idx & 31) * 4;
                *(float4*)&Bs[r * LDB + cg] = *(const float4*)(B + (size_t)(k0 + r) * 128 + cg);
            }
            __syncthreads();
            mma_panel(As + k0, LDA, Bs, LDB, acc, wr, wc);
            __syncthreads();
        }
#pragma unroll
        for (int i = 0; i < 2; ++i)
#pragma unroll
            for (int j = 0; j < 4; ++j)
                wmma::store_matrix_sync(&S[(size_t)(wr * 32 + i * 16) * LDS + wc * 64 + j * 16],
                                        acc[i][j], LDS, wmma::mem_row_major);
        __syncthreads();
        for (int idx = tid; idx < 128 * 128; idx += 256) {
            int r = idx >> 7, c = idx & 127;
            Out[(size_t)(rowBase + r) * 128 + c] = S[r * LDS + c] + bias[c];
        }
        __syncthreads();
    }
}

// ---------------- scores + segment max ---------------------------------------
__global__ void score_kernel(const int* __restrict__ dst) {
    int gid = blockIdx.x * blockDim.x + threadIdx.x;
    if (gid >= NEDGE * NH) return;
    int e = gid >> 3, h = gid & 7;
    int d = dst[e];
    const float4* kp = (const float4*)(g_k + (size_t)e * 128 + h * 16);
    const float4* qp = (const float4*)(g_q + (size_t)d * 128 + h * 16);
    float s = 0.f;
#pragma unroll
    for (int i = 0; i < 4; ++i) {
        float4 kv = kp[i], qv = qp[i];
        s += kv.x * qv.x + kv.y * qv.y + kv.z * qv.z + kv.w * qv.w;
    }
    s *= 0.25f;   // / sqrt(16)
    g_sc[gid] = s;
    atomicMax(&g_smax[d * NH + h], fenc(s));
}

// ---------------- exp + segment sum ------------------------------------------
__global__ void expsum_kernel(const int* __restrict__ dst) {
    int gid = blockIdx.x * blockDim.x + threadIdx.x;
    if (gid >= NEDGE * NH) return;
    int e = gid >> 3, h = gid & 7;
    int d = dst[e];
    float mx = fdec(g_smax[d * NH + h]);
    float ex = expf(g_sc[gid] - mx);
    g_sc[gid] = ex;
    atomicAdd(&g_den[d * NH + h], ex);
}

// ---------------- weighted scatter of v (vector red) -------------------------
__global__ void scatter_kernel(const int* __restrict__ dst) {
    int gid = blockIdx.x * blockDim.x + threadIdx.x;
    if (gid >= NEDGE * 32) return;
    int e = gid >> 5, t = gid & 31;
    int d0 = t * 4;
    int h = d0 >> 4;
    int d = dst[e];
    float alpha = g_sc[(size_t)e * NH + h] / (g_den[d * NH + h] + 1e-16f);
    float4 vv = *(const float4*)(g_v + (size_t)e * 128 + d0);
    float* ap = g_agg + (size_t)d * 128 + d0;
    asm volatile("red.global.add.v4.f32 [%0], {%1,%2,%3,%4};"
                 :: "l"(ap), "f"(alpha * vv.x), "f"(alpha * vv.y),
                    "f"(alpha * vv.z), "f"(alpha * vv.w) : "memory");
}

// ---------------- launch ------------------------------------------------------
extern "C" void kernel_launch(void* const* d_in, const int* in_sizes, int n_in,
                              void* d_out, int out_size) {
    const float* x     = (const float*)d_in[0];
    const float* t     = (const float*)d_in[1];
    const float* f_ij  = (const float*)d_in[2];
    const float* r_ij  = (const float*)d_in[3];
    const int*   src   = (const int*)d_in[4];
    const int*   dst   = (const int*)d_in[5];
    const float* W_lin = (const float*)d_in[6];
    const float* b_lin = (const float*)d_in[7];
    const float* W_r1  = (const float*)d_in[8];
    const float* b_r1  = (const float*)d_in[9];
    const float* W_r2  = (const float*)d_in[10];
    const float* b_r2  = (const float*)d_in[11];
    const float* Wq    = (const float*)d_in[12];
    const float* bq    = (const float*)d_in[13];
    const float* Wk    = (const float*)d_in[14];
    const float* bk    = (const float*)d_in[15];
    const float* Wv    = (const float*)d_in[16];
    const float* bv    = (const float*)d_in[17];
    const float* Wo    = (const float*)d_in[18];
    const float* bo    = (const float*)d_in[19];
    const float* ln_g  = (const float*)d_in[20];
    const float* ln_b  = (const float*)d_in[21];
    float* out = (float*)d_out;

    float *ph, *pq, *pagg;
    cudaGetSymbolAddress((void**)&ph,   g_h);
    cudaGetSymbolAddress((void**)&pq,   g_q);
    cudaGetSymbolAddress((void**)&pagg, g_agg);

    const int SM_NODE   = (128 * 36 + 32 * 132 + 128 * 132) * 4;              // 102912
    const int SM_FILTER = (128 * 68 + 128 * 132 + 32 * 132) * 4;              // 119296
    const int SM_KV     = (128 * 132 + 32 * 132 + 128 * 132) * 4;             // 152064
    cudaFuncSetAttribute(node_gemm<0>, cudaFuncAttributeMaxDynamicSharedMemorySize, SM_NODE);
    cudaFuncSetAttribute(node_gemm<3>, cudaFuncAttributeMaxDynamicSharedMemorySize, SM_NODE);
    cudaFuncSetAttribute(filter_kernel, cudaFuncAttributeMaxDynamicSharedMemorySize, SM_FILTER);
    cudaFuncSetAttribute(kv_kernel, cudaFuncAttributeMaxDynamicSharedMemorySize, SM_KV);

    const int TB = 256;
    int gridN   = (NNODE * Dm + TB - 1) / TB;      // 20000
    int gridE8  = (NEDGE * NH + TB - 1) / TB;      // 20000
    int gridE32 = (NEDGE * 32 + TB - 1) / TB;      // 80000
    int gemmE   = NEDGE / 128;                     // 5000 (exact)
    int gemmN   = (NNODE + 127) / 128;             // 313

    init_kernel<<<gridN, TB>>>();
    add_h_kernel<<<gridN, TB>>>(x, t);

    // q = h @ Wq + bq
    node_gemm<0><<<gemmN, TB, SM_NODE>>>(ph, Wq, bq, pq, NNODE, nullptr, nullptr, nullptr);

    // m = h[src] * (f@W_lin + b_lin + ssp(f@W_r1+b_r1)@W_r2 + b_r2) * cutoff(r)
    filter_kernel<<<gemmE, TB, SM_FILTER>>>(f_ij, W_r1, b_r1, W_lin, b_lin,
                                            W_r2, b_r2, r_ij, src);

    // k = m@Wk+bk ; v = m@Wv+bv (one pass over m)
    kv_kernel<<<gemmE, TB, SM_KV>>>(Wk, bk, Wv, bv);

    score_kernel<<<gridE8, TB>>>(dst);
    expsum_kernel<<<gridE8, TB>>>(dst);
    scatter_kernel<<<gridE32, TB>>>(dst);

    // out = LN(x + agg @ Wo + bo)
    node_gemm<3><<<gemmN, TB, SM_NODE>>>(pagg, Wo, bo, out, NNODE, x, ln_g, ln_b);
}

// round 4
// speedup vs baseline: 2.2892x; 2.2302x over previous
#include <cuda_runtime.h>
#include <cuda_bf16.h>
#include <mma.h>
using namespace nvcuda;
typedef __nv_bfloat16 bf16;

#define Dm 128
#define NH 8
#define NNODE 40000
#define NEDGE 640000

// ---------------- scratch (static device globals) -----------------------------
__device__ bf16  g_hh[(size_t)NNODE * Dm];     // h = x+t, bf16
__device__ float g_q[(size_t)NNODE * Dm];      // queries fp32
__device__ bf16  g_vh[(size_t)NEDGE * Dm];     // values bf16
__device__ float g_sc[(size_t)NEDGE * NH];     // scores -> exp
__device__ unsigned g_smax[(size_t)NNODE * NH];
__device__ float g_den[(size_t)NNODE * NH];
__device__ float g_agg[(size_t)NNODE * Dm];
// bf16 weights
__device__ bf16 g_Wr1h[64 * 128];
__device__ bf16 g_Wlinh[64 * 128];
__device__ bf16 g_Wr2h[128 * 128];
__device__ bf16 g_Wqh[128 * 128];
__device__ bf16 g_Wkh[128 * 128];
__device__ bf16 g_Wvh[128 * 128];
__device__ bf16 g_Woh[128 * 128];

// ---------------- helpers ------------------------------------------------------
__device__ __forceinline__ unsigned fenc(float f) {
    unsigned u = __float_as_uint(f);
    return (u & 0x80000000u) ? ~u : (u | 0x80000000u);
}
__device__ __forceinline__ float fdec(unsigned u) {
    return __uint_as_float((u & 0x80000000u) ? (u ^ 0x80000000u) : ~u);
}
#define SMAX_INIT 0x007fffffu

__device__ __forceinline__ float sspf(float v) {
    float sp = (v > 20.f) ? v : log1pf(expf(v));
    return sp - 0.6931471805599453f;
}
__device__ __forceinline__ float cutoff(float r) {
    float c = 0.5f * (cosf(r * 0.39269908169872414f) + 1.f);
    return (r < 8.f) ? c : 0.f;
}
// store 4 floats as 4 bf16 (dst must be 8B aligned)
__device__ __forceinline__ void st_bf4(bf16* p, float4 v) {
    __nv_bfloat162 a = __floats2bfloat162_rn(v.x, v.y);
    __nv_bfloat162 b = __floats2bfloat162_rn(v.z, v.w);
    uint2 u; u.x = *(unsigned*)&a; u.y = *(unsigned*)&b;
    *(uint2*)p = u;
}

// ---------------- small kernels ------------------------------------------------
__global__ void convert_kernel(const float* __restrict__ src, bf16* __restrict__ dst, int n) {
    for (int i = blockIdx.x * blockDim.x + threadIdx.x; i < n; i += gridDim.x * blockDim.x)
        dst[i] = __float2bfloat16(src[i]);
}
__global__ void init_kernel() {
    int gid = blockIdx.x * blockDim.x + threadIdx.x;
    if (gid < NNODE * Dm) g_agg[gid] = 0.f;
    if (gid < NNODE * NH) { g_den[gid] = 0.f; g_smax[gid] = SMAX_INIT; }
}
__global__ void add_h_kernel(const float* __restrict__ x, const float* __restrict__ t) {
    int gid = blockIdx.x * blockDim.x + threadIdx.x;
    if (gid < NNODE * Dm) g_hh[gid] = __float2bfloat16(x[gid] + t[gid]);
}

// ---------------- wmma bf16 machinery ------------------------------------------
typedef wmma::fragment<wmma::matrix_a, 16, 16, 16, bf16, wmma::row_major> HA;
typedef wmma::fragment<wmma::matrix_b, 16, 16, 16, bf16, wmma::row_major> HB;
typedef wmma::fragment<wmma::accumulator, 16, 16, 16, float> HC;

// warp grid 4x4 over 128x128 CTA tile; warp tile 32x32 -> acc[2][2]
__device__ __forceinline__ void mma_panel_h(const bf16* As, int lda,
                                            const bf16* Bs, int ldb,
                                            HC (&acc)[2][2], int wr, int wc, int ksteps) {
    for (int kk = 0; kk < ksteps; ++kk) {
        HA a[2]; HB b[2];
#pragma unroll
        for (int i = 0; i < 2; ++i)
            wmma::load_matrix_sync(a[i], As + (size_t)(wr * 32 + i * 16) * lda + kk * 16, lda);
#pragma unroll
        for (int j = 0; j < 2; ++j)
            wmma::load_matrix_sync(b[j], Bs + (size_t)(kk * 16) * ldb + wc * 32 + j * 16, ldb);
#pragma unroll
        for (int i = 0; i < 2; ++i)
#pragma unroll
            for (int j = 0; j < 2; ++j) wmma::mma_sync(acc[i][j], a[i], b[j], acc[i][j]);
    }
}
__device__ __forceinline__ void acc_zero(HC (&acc)[2][2]) {
#pragma unroll
    for (int i = 0; i < 2; ++i)
#pragma unroll
        for (int j = 0; j < 2; ++j) wmma::fill_fragment(acc[i][j], 0.f);
}
__device__ __forceinline__ void acc_store(float* S, HC (&acc)[2][2], int wr, int wc) {
#pragma unroll
    for (int i = 0; i < 2; ++i)
#pragma unroll
        for (int j = 0; j < 2; ++j)
            wmma::store_matrix_sync(S + (size_t)(wr * 32 + i * 16) * 132 + wc * 32 + j * 16,
                                    acc[i][j], 132, wmma::mem_row_major);
}
// load bf16 weight [rows x 128] into Bs (LDB=136); 512 threads
__device__ __forceinline__ void load_weight(bf16* Bs, const bf16* W, int rows, int tid) {
    int n = rows * 16;  // uint4 count (8 elems each)
    for (int idx = tid; idx < n; idx += 512) {
        int r = idx >> 4, c8 = (idx & 15) * 8;
        *(uint4*)&Bs[r * 136 + c8] = *(const uint4*)(W + (size_t)r * 128 + c8);
    }
}

// ---------------- node GEMM (bf16 mma): MODE 0 = +bias; MODE 3 = resid+LN ------
// AB16: A already bf16 (global), else fp32 converted on load.
template <int MODE, bool AB16>
__global__ __launch_bounds__(512)
void node_gemm_h(const void* __restrict__ Ain, const bf16* __restrict__ W,
                 const float* __restrict__ bias, float* __restrict__ C, int M,
                 const float* __restrict__ resid,
                 const float* __restrict__ ln_g, const float* __restrict__ ln_b)
{
    extern __shared__ char smraw[];
    float* S  = (float*)smraw;                        // 128*132 f32
    bf16*  As = (bf16*)(smraw + 128 * 132 * 4);       // 128*136
    bf16*  Bs = As + 128 * 136;                       // 128*136
    const int tid = threadIdx.x, wid = tid >> 5;
    const int wr = wid >> 2, wc = wid & 3;
    const int rowBase = blockIdx.x * 128;

    if constexpr (AB16) {
        const bf16* A = (const bf16*)Ain;
#pragma unroll
        for (int p = 0; p < 4; ++p) {
            int idx = tid + p * 512;
            int r = idx >> 4, c8 = (idx & 15) * 8;
            int gr = rowBase + r;
            uint4 v = make_uint4(0, 0, 0, 0);
            if (gr < M) v = *(const uint4*)(A + (size_t)gr * 128 + c8);
            *(uint4*)&As[r * 136 + c8] = v;
        }
    } else {
        const float* A = (const float*)Ain;
#pragma unroll
        for (int p = 0; p < 8; ++p) {
            int idx = tid + p * 512;
            int r = idx >> 5, cg = (idx & 31) * 4;
            int gr = rowBase + r;
            float4 v = make_float4(0.f, 0.f, 0.f, 0.f);
            if (gr < M) v = *(const float4*)(A + (size_t)gr * 128 + cg);
            st_bf4(&As[r * 136 + cg], v);
        }
    }
    load_weight(Bs, W, 128, tid);
    __syncthreads();

    HC acc[2][2];
    acc_zero(acc);
    mma_panel_h(As, 136, Bs, 136, acc, wr, wc, 8);
    __syncthreads();
    acc_store(S, acc, wr, wc);
    __syncthreads();

    if constexpr (MODE == 0) {
        for (int idx = tid; idx < 4096; idx += 512) {
            int r = idx >> 5, cq = (idx & 31) * 4;
            int gr = rowBase + r;
            if (gr < M) {
                float4 s = *(const float4*)&S[r * 132 + cq];
                s.x += bias[cq]; s.y += bias[cq + 1]; s.z += bias[cq + 2]; s.w += bias[cq + 3];
                *(float4*)(C + (size_t)gr * 128 + cq) = s;
            }
        }
    } else {
        __shared__ float muS[128], invS[128];
        for (int idx = tid; idx < 4096; idx += 512) {
            int r = idx >> 5, cq = (idx & 31) * 4;
            int gr = rowBase + r;
            if (gr < M) {
                float4 s = *(const float4*)&S[r * 132 + cq];
                float4 rr = *(const float4*)(resid + (size_t)gr * 128 + cq);
                s.x += bias[cq] + rr.x;     s.y += bias[cq + 1] + rr.y;
                s.z += bias[cq + 2] + rr.z; s.w += bias[cq + 3] + rr.w;
                *(float4*)&S[r * 132 + cq] = s;
            }
        }
        __syncthreads();
        if (tid < 128) {
            int gr = rowBase + tid;
            if (gr < M) {
                float s = 0.f, q2 = 0.f;
#pragma unroll 4
                for (int c = 0; c < 128; ++c) { float v = S[tid * 132 + c]; s += v; q2 += v * v; }
                float mean = s * (1.f / 128.f);
                float var = q2 * (1.f / 128.f) - mean * mean;
                muS[tid] = mean; invS[tid] = rsqrtf(var + 1e-5f);
            }
        }
        __syncthreads();
        for (int idx = tid; idx < 4096; idx += 512) {
            int r = idx >> 5, cq = (idx & 31) * 4;
            int gr = rowBase + r;
            if (gr < M) {
                float4 s = *(const float4*)&S[r * 132 + cq];
                float4 o;
                o.x = (s.x - muS[r]) * invS[r] * ln_g[cq]     + ln_b[cq];
                o.y = (s.y - muS[r]) * invS[r] * ln_g[cq + 1] + ln_b[cq + 1];
                o.z = (s.z - muS[r]) * invS[r] * ln_g[cq + 2] + ln_b[cq + 2];
                o.w = (s.w - muS[r]) * invS[r] * ln_g[cq + 3] + ln_b[cq + 3];
                *(float4*)(C + (size_t)gr * 128 + cq) = o;
            }
        }
    }
}

// ---------------- mega edge kernel: filter + k/v + scores ----------------------
// per 128-edge tile:
//   U = ssp(f@Wr1+br1); m = hh[src]*(f@Wlin + U@Wr2 + blin + br2)*C(r)
//   k = m@Wk (+bk in epilogue) -> scores (q[dst] dot) + atomicMax
//   v = m@Wv + bv -> g_vh (bf16)
__global__ __launch_bounds__(512)
void edge_fused_kernel(const float* __restrict__ f_ij, const float* __restrict__ r_ij,
                       const int* __restrict__ src, const int* __restrict__ dst,
                       const float* __restrict__ b_r1, const float* __restrict__ b_lin,
                       const float* __restrict__ b_r2,
                       const float* __restrict__ bk, const float* __restrict__ bv)
{
    extern __shared__ char smraw[];
    float* S  = (float*)smraw;                         // 128*132 f32   67584 B
    bf16*  Fs = (bf16*)(smraw + 67584);                // 128*72        18432 B
    bf16*  Ms = (bf16*)(smraw + 67584 + 18432);        // 128*136       34816 B
    bf16*  Bs = (bf16*)(smraw + 67584 + 18432 + 34816);// 128*136       34816 B
    __shared__ float Ce[128];
    __shared__ int   srcs[128], dsts[128];

    const int tid = threadIdx.x, wid = tid >> 5;
    const int wr = wid >> 2, wc = wid & 3;
    const int rowBase = blockIdx.x * 128;   // NEDGE = 5000*128 exactly

    // load f tile (fp32 -> bf16), edge metadata
#pragma unroll
    for (int p = 0; p < 4; ++p) {
        int idx = tid + p * 512;
        int r = idx >> 4, cg = (idx & 15) * 4;
        float4 v = *(const float4*)(f_ij + (size_t)(rowBase + r) * 64 + cg);
        st_bf4(&Fs[r * 72 + cg], v);
    }
    if (tid < 128) {
        int e = rowBase + tid;
        Ce[tid] = cutoff(r_ij[e]);
        srcs[tid] = src[e];
        dsts[tid] = dst[e];
    }

    HC acc[2][2];

    // ---- stage 1: U = ssp(f @ Wr1 + br1) ----
    acc_zero(acc);
    load_weight(Bs, g_Wr1h, 64, tid);
    __syncthreads();
    mma_panel_h(Fs, 72, Bs, 136, acc, wr, wc, 4);
    __syncthreads();
    acc_store(S, acc, wr, wc);
    __syncthreads();
    for (int idx = tid; idx < 4096; idx += 512) {
        int r = idx >> 5, cq = (idx & 31) * 4;
        float4 s = *(const float4*)&S[r * 132 + cq];
        float4 u;
        u.x = sspf(s.x + b_r1[cq]);     u.y = sspf(s.y + b_r1[cq + 1]);
        u.z = sspf(s.z + b_r1[cq + 2]); u.w = sspf(s.w + b_r1[cq + 3]);
        st_bf4(&Ms[r * 136 + cq], u);
    }

    // ---- stage 2: W = f@Wlin + U@Wr2 ----
    acc_zero(acc);
    load_weight(Bs, g_Wlinh, 64, tid);
    __syncthreads();          // covers U-epilogue writes + Bs load
    mma_panel_h(Fs, 72, Bs, 136, acc, wr, wc, 4);
    __syncthreads();
    load_weight(Bs, g_Wr2h, 128, tid);
    __syncthreads();
    mma_panel_h(Ms, 136, Bs, 136, acc, wr, wc, 8);
    __syncthreads();
    acc_store(S, acc, wr, wc);
    __syncthreads();
    // m epilogue: Ms <- bf16(h[src]*(S+blin+br2)*Ce)
    for (int idx = tid; idx < 4096; idx += 512) {
        int r = idx >> 5, cq = (idx & 31) * 4;
        float4 s = *(const float4*)&S[r * 132 + cq];
        uint2 hr = *(const uint2*)(g_hh + (size_t)srcs[r] * 128 + cq);
        float2 h0 = __bfloat1622float2(*(__nv_bfloat162*)&hr.x);
        float2 h1 = __bfloat1622float2(*(__nv_bfloat162*)&hr.y);
        float ce = Ce[r];
        float4 m;
        m.x = h0.x * (s.x + b_lin[cq]     + b_r2[cq])     * ce;
        m.y = h0.y * (s.y + b_lin[cq + 1] + b_r2[cq + 1]) * ce;
        m.z = h1.x * (s.z + b_lin[cq + 2] + b_r2[cq + 2]) * ce;
        m.w = h1.y * (s.w + b_lin[cq + 3] + b_r2[cq + 3]) * ce;
        st_bf4(&Ms[r * 136 + cq], m);
    }

    // ---- k stage: k = m@Wk, scores epilogue ----
    acc_zero(acc);
    load_weight(Bs, g_Wkh, 128, tid);
    __syncthreads();          // covers m-epilogue + Bs load
    mma_panel_h(Ms, 136, Bs, 136, acc, wr, wc, 8);
    __syncthreads();
    acc_store(S, acc, wr, wc);
    __syncthreads();
    // scores: 128 edges x 8 heads, DH=16
    for (int t = tid; t < 1024; t += 512) {
        int r = t >> 3, h = t & 7;
        int d = dsts[r];
        const float* kp = &S[r * 132 + h * 16];
        const float4* qp = (const float4*)(g_q + (size_t)d * 128 + h * 16);
        const float* bb = bk + h * 16;
        float s = 0.f;
#pragma unroll
        for (int i = 0; i < 4; ++i) {
            float4 qv = qp[i];
            s += (kp[i * 4 + 0] + bb[i * 4 + 0]) * qv.x;
            s += (kp[i * 4 + 1] + bb[i * 4 + 1]) * qv.y;
            s += (kp[i * 4 + 2] + bb[i * 4 + 2]) * qv.z;
            s += (kp[i * 4 + 3] + bb[i * 4 + 3]) * qv.w;
        }
        s *= 0.25f;
        g_sc[(size_t)(rowBase + r) * NH + h] = s;
        atomicMax(&g_smax[d * NH + h], fenc(s));
    }

    // ---- v stage: v = m@Wv + bv -> bf16 ----
    acc_zero(acc);
    load_weight(Bs, g_Wvh, 128, tid);
    __syncthreads();          // covers score epilogue reads of S
    mma_panel_h(Ms, 136, Bs, 136, acc, wr, wc, 8);
    __syncthreads();
    acc_store(S, acc, wr, wc);
    __syncthreads();
    for (int idx = tid; idx < 4096; idx += 512) {
        int r = idx >> 5, cq = (idx & 31) * 4;
        float4 s = *(const float4*)&S[r * 132 + cq];
        s.x += bv[cq]; s.y += bv[cq + 1]; s.z += bv[cq + 2]; s.w += bv[cq + 3];
        st_bf4(&g_vh[(size_t)(rowBase + r) * 128 + cq], s);
    }
}

// ---------------- exp + segment sum --------------------------------------------
__global__ void expsum_kernel(const int* __restrict__ dst) {
    int gid = blockIdx.x * blockDim.x + threadIdx.x;
    if (gid >= NEDGE * NH) return;
    int e = gid >> 3, h = gid & 7;
    int d = dst[e];
    float mx = fdec(g_smax[d * NH + h]);
    float ex = expf(g_sc[gid] - mx);
    g_sc[gid] = ex;
    atomicAdd(&g_den[d * NH + h], ex);
}

// ---------------- weighted scatter of v (bf16 read, v4 red) --------------------
__global__ void scatter_kernel(const int* __restrict__ dst) {
    int gid = blockIdx.x * blockDim.x + threadIdx.x;
    if (gid >= NEDGE * 32) return;
    int e = gid >> 5, t = gid & 31;
    int d0 = t * 4;
    int h = d0 >> 4;
    int d = dst[e];
    float alpha = g_sc[(size_t)e * NH + h] / (g_den[d * NH + h] + 1e-16f);
    uint2 raw = *(const uint2*)(g_vh + (size_t)e * 128 + d0);
    float2 v0 = __bfloat1622float2(*(__nv_bfloat162*)&raw.x);
    float2 v1 = __bfloat1622float2(*(__nv_bfloat162*)&raw.y);
    float* ap = g_agg + (size_t)d * 128 + d0;
    asm volatile("red.global.add.v4.f32 [%0], {%1,%2,%3,%4};"
                 :: "l"(ap), "f"(alpha * v0.x), "f"(alpha * v0.y),
                    "f"(alpha * v1.x), "f"(alpha * v1.y) : "memory");
}

// ---------------- launch --------------------------------------------------------
extern "C" void kernel_launch(void* const* d_in, const int* in_sizes, int n_in,
                              void* d_out, int out_size) {
    const float* x     = (const float*)d_in[0];
    const float* t     = (const float*)d_in[1];
    const float* f_ij  = (const float*)d_in[2];
    const float* r_ij  = (const float*)d_in[3];
    const int*   src   = (const int*)d_in[4];
    const int*   dst   = (const int*)d_in[5];
    const float* W_lin = (const float*)d_in[6];
    const float* b_lin = (const float*)d_in[7];
    const float* W_r1  = (const float*)d_in[8];
    const float* b_r1  = (const float*)d_in[9];
    const float* W_r2  = (const float*)d_in[10];
    const float* b_r2  = (const float*)d_in[11];
    const float* Wq    = (const float*)d_in[12];
    const float* bq    = (const float*)d_in[13];
    const float* Wk    = (const float*)d_in[14];
    const float* bk    = (const float*)d_in[15];
    const float* Wv    = (const float*)d_in[16];
    const float* bv    = (const float*)d_in[17];
    const float* Wo    = (const float*)d_in[18];
    const float* bo    = (const float*)d_in[19];
    const float* ln_g  = (const float*)d_in[20];
    const float* ln_b  = (const float*)d_in[21];
    float* out = (float*)d_out;

    bf16 *pWr1h, *pWlinh, *pWr2h, *pWqh, *pWkh, *pWvh, *pWoh, *phh;
    float *pq, *pagg;
    cudaGetSymbolAddress((void**)&pWr1h, g_Wr1h);
    cudaGetSymbolAddress((void**)&pWlinh, g_Wlinh);
    cudaGetSymbolAddress((void**)&pWr2h, g_Wr2h);
    cudaGetSymbolAddress((void**)&pWqh, g_Wqh);
    cudaGetSymbolAddress((void**)&pWkh, g_Wkh);
    cudaGetSymbolAddress((void**)&pWvh, g_Wvh);
    cudaGetSymbolAddress((void**)&pWoh, g_Woh);
    cudaGetSymbolAddress((void**)&phh, g_hh);
    cudaGetSymbolAddress((void**)&pq,  g_q);
    cudaGetSymbolAddress((void**)&pagg, g_agg);

    const int SM_NODE = 128 * 132 * 4 + 2 * (128 * 136 * 2);   // 137216
    const int SM_EDGE = 67584 + 18432 + 2 * 34816;             // 155648
    cudaFuncSetAttribute((const void*)node_gemm_h<0, true>,  cudaFuncAttributeMaxDynamicSharedMemorySize, SM_NODE);
    cudaFuncSetAttribute((const void*)node_gemm_h<3, false>, cudaFuncAttributeMaxDynamicSharedMemorySize, SM_NODE);
    cudaFuncSetAttribute((const void*)edge_fused_kernel,     cudaFuncAttributeMaxDynamicSharedMemorySize, SM_EDGE);

    // weight conversion (tiny)
    convert_kernel<<<16, 512>>>(W_r1, pWr1h, 64 * 128);
    convert_kernel<<<16, 512>>>(W_lin, pWlinh, 64 * 128);
    convert_kernel<<<32, 512>>>(W_r2, pWr2h, 128 * 128);
    convert_kernel<<<32, 512>>>(Wq, pWqh, 128 * 128);
    convert_kernel<<<32, 512>>>(Wk, pWkh, 128 * 128);
    convert_kernel<<<32, 512>>>(Wv, pWvh, 128 * 128);
    convert_kernel<<<32, 512>>>(Wo, pWoh, 128 * 128);

    const int TB = 256;
    int gridN   = (NNODE * Dm + TB - 1) / TB;
    int gridE8  = (NEDGE * NH + TB - 1) / TB;
    int gridE32 = (NEDGE * 32 + TB - 1) / TB;
    int gemmE   = NEDGE / 128;         // 5000
    int gemmN   = (NNODE + 127) / 128; // 313

    init_kernel<<<gridN, TB>>>();
    add_h_kernel<<<gridN, TB>>>(x, t);

    // q = h @ Wq + bq   (A already bf16)
    node_gemm_h<0, true><<<gemmN, 512, SM_NODE>>>(phh, pWqh, bq, pq, NNODE,
                                                  nullptr, nullptr, nullptr);

    // fused filter + k/v + scores
    edge_fused_kernel<<<gemmE, 512, SM_EDGE>>>(f_ij, r_ij, src, dst,
                                               b_r1, b_lin, b_r2, bk, bv);

    expsum_kernel<<<gridE8, TB>>>(dst);
    scatter_kernel<<<gridE32, TB>>>(dst);

    // out = LN(x + agg @ Wo + bo)
    node_gemm_h<3, false><<<gemmN, 512, SM_NODE>>>(pagg, pWoh, bo, out, NNODE,
                                                   x, ln_g, ln_b);
}

// round 5
// speedup vs baseline: 2.3183x; 1.0127x over previous
#include <cuda_runtime.h>
#include <cuda_bf16.h>
#include <mma.h>
using namespace nvcuda;
typedef __nv_bfloat16 bf16;

#define Dm 128
#define NH 8
#define NNODE 40000
#define NEDGE 640000

// ---------------- scratch (static device globals) -----------------------------
__device__ bf16  g_hh[(size_t)NNODE * Dm];     // h = x+t, bf16
__device__ float g_q[(size_t)NNODE * Dm];      // queries fp32
__device__ bf16  g_vh[(size_t)NEDGE * Dm];     // values bf16
__device__ float g_sc[(size_t)NEDGE * NH];     // raw scores
__device__ unsigned g_smax[(size_t)NNODE * NH];
__device__ float g_agg[(size_t)NNODE * Dm];
// CSR build
__device__ int g_cnt[NNODE];
__device__ int g_cur[NNODE];
__device__ int g_off[NNODE + 1];
__device__ int g_eid[NEDGE];
// bf16 weights
__device__ bf16 g_Wr1h[64 * 128];
__device__ bf16 g_Wlinh[64 * 128];
__device__ bf16 g_Wr2h[128 * 128];
__device__ bf16 g_Wqh[128 * 128];
__device__ bf16 g_Wkh[128 * 128];
__device__ bf16 g_Wvh[128 * 128];
__device__ bf16 g_Woh[128 * 128];

// ---------------- helpers ------------------------------------------------------
__device__ __forceinline__ unsigned fenc(float f) {
    unsigned u = __float_as_uint(f);
    return (u & 0x80000000u) ? ~u : (u | 0x80000000u);
}
__device__ __forceinline__ float fdec(unsigned u) {
    return __uint_as_float((u & 0x80000000u) ? (u ^ 0x80000000u) : ~u);
}
#define SMAX_INIT 0x007fffffu

__device__ __forceinline__ float sspf(float v) {
    float sp = (v > 20.f) ? v : log1pf(expf(v));
    return sp - 0.6931471805599453f;
}
__device__ __forceinline__ float cutoff(float r) {
    float c = 0.5f * (cosf(r * 0.39269908169872414f) + 1.f);
    return (r < 8.f) ? c : 0.f;
}
__device__ __forceinline__ void st_bf4(bf16* p, float4 v) {
    __nv_bfloat162 a = __floats2bfloat162_rn(v.x, v.y);
    __nv_bfloat162 b = __floats2bfloat162_rn(v.z, v.w);
    uint2 u; u.x = *(unsigned*)&a; u.y = *(unsigned*)&b;
    *(uint2*)p = u;
}

// ---------------- small kernels ------------------------------------------------
__global__ void convert_kernel(const float* __restrict__ src, bf16* __restrict__ dst, int n) {
    for (int i = blockIdx.x * blockDim.x + threadIdx.x; i < n; i += gridDim.x * blockDim.x)
        dst[i] = __float2bfloat16(src[i]);
}
__global__ void init_kernel() {
    int gid = blockIdx.x * blockDim.x + threadIdx.x;
    if (gid < NNODE) { g_cnt[gid] = 0; g_cur[gid] = 0; }
    if (gid < NNODE * NH) g_smax[gid] = SMAX_INIT;
}
__global__ void add_h_kernel(const float* __restrict__ x, const float* __restrict__ t) {
    int gid = blockIdx.x * blockDim.x + threadIdx.x;
    if (gid < NNODE * Dm) g_hh[gid] = __float2bfloat16(x[gid] + t[gid]);
}

// ---------------- CSR build: hist -> scan -> id scatter ------------------------
__global__ void hist_kernel(const int* __restrict__ dst) {
    int e = blockIdx.x * blockDim.x + threadIdx.x;
    if (e < NEDGE) atomicAdd(&g_cnt[dst[e]], 1);
}
__global__ __launch_bounds__(1024) void scan_kernel() {
    __shared__ int part[1024];
    const int C = (NNODE + 1023) / 1024;        // 40
    int t = threadIdx.x;
    int base = t * C;
    int s = 0;
    for (int i = 0; i < C; ++i) {
        int idx = base + i;
        if (idx < NNODE) s += g_cnt[idx];
    }
    part[t] = s;
    __syncthreads();
    // Hillis-Steele inclusive scan
    for (int d = 1; d < 1024; d <<= 1) {
        int v = (t >= d) ? part[t - d] : 0;
        __syncthreads();
        part[t] += v;
        __syncthreads();
    }
    int run = part[t] - s;     // exclusive prefix for this thread's chunk
    for (int i = 0; i < C; ++i) {
        int idx = base + i;
        if (idx < NNODE) { g_off[idx] = run; run += g_cnt[idx]; }
    }
    if (t == 1023) g_off[NNODE] = run;
}
__global__ void idscatter_kernel(const int* __restrict__ dst) {
    int e = blockIdx.x * blockDim.x + threadIdx.x;
    if (e < NEDGE) {
        int d = dst[e];
        int p = g_off[d] + atomicAdd(&g_cur[d], 1);
        g_eid[p] = e;
    }
}

// ---------------- wmma bf16 machinery ------------------------------------------
typedef wmma::fragment<wmma::matrix_a, 16, 16, 16, bf16, wmma::row_major> HA;
typedef wmma::fragment<wmma::matrix_b, 16, 16, 16, bf16, wmma::row_major> HB;
typedef wmma::fragment<wmma::accumulator, 16, 16, 16, float> HC;

__device__ __forceinline__ void mma_panel_h(const bf16* As, int lda,
                                            const bf16* Bs, int ldb,
                                            HC (&acc)[2][2], int wr, int wc, int ksteps) {
    for (int kk = 0; kk < ksteps; ++kk) {
        HA a[2]; HB b[2];
#pragma unroll
        for (int i = 0; i < 2; ++i)
            wmma::load_matrix_sync(a[i], As + (size_t)(wr * 32 + i * 16) * lda + kk * 16, lda);
#pragma unroll
        for (int j = 0; j < 2; ++j)
            wmma::load_matrix_sync(b[j], Bs + (size_t)(kk * 16) * ldb + wc * 32 + j * 16, ldb);
#pragma unroll
        for (int i = 0; i < 2; ++i)
#pragma unroll
            for (int j = 0; j < 2; ++j) wmma::mma_sync(acc[i][j], a[i], b[j], acc[i][j]);
    }
}
__device__ __forceinline__ void acc_zero(HC (&acc)[2][2]) {
#pragma unroll
    for (int i = 0; i < 2; ++i)
#pragma unroll
        for (int j = 0; j < 2; ++j) wmma::fill_fragment(acc[i][j], 0.f);
}
__device__ __forceinline__ void acc_store(float* S, HC (&acc)[2][2], int wr, int wc) {
#pragma unroll
    for (int i = 0; i < 2; ++i)
#pragma unroll
        for (int j = 0; j < 2; ++j)
            wmma::store_matrix_sync(S + (size_t)(wr * 32 + i * 16) * 132 + wc * 32 + j * 16,
                                    acc[i][j], 132, wmma::mem_row_major);
}
__device__ __forceinline__ void load_weight(bf16* Bs, const bf16* W, int rows, int tid) {
    int n = rows * 16;
    for (int idx = tid; idx < n; idx += 512) {
        int r = idx >> 4, c8 = (idx & 15) * 8;
        *(uint4*)&Bs[r * 136 + c8] = *(const uint4*)(W + (size_t)r * 128 + c8);
    }
}

// ---------------- node GEMM: MODE 0 = +bias; MODE 3 = resid+LN -----------------
template <int MODE, bool AB16>
__global__ __launch_bounds__(512)
void node_gemm_h(const void* __restrict__ Ain, const bf16* __restrict__ W,
                 const float* __restrict__ bias, float* __restrict__ C, int M,
                 const float* __restrict__ resid,
                 const float* __restrict__ ln_g, const float* __restrict__ ln_b)
{
    extern __shared__ char smraw[];
    float* S  = (float*)smraw;                        // 128*132 f32
    bf16*  As = (bf16*)(smraw + 128 * 132 * 4);       // 128*136
    bf16*  Bs = As + 128 * 136;                       // 128*136
    const int tid = threadIdx.x, wid = tid >> 5;
    const int wr = wid >> 2, wc = wid & 3;
    const int rowBase = blockIdx.x * 128;

    if constexpr (AB16) {
        const bf16* A = (const bf16*)Ain;
#pragma unroll
        for (int p = 0; p < 4; ++p) {
            int idx = tid + p * 512;
            int r = idx >> 4, c8 = (idx & 15) * 8;
            int gr = rowBase + r;
            uint4 v = make_uint4(0, 0, 0, 0);
            if (gr < M) v = *(const uint4*)(A + (size_t)gr * 128 + c8);
            *(uint4*)&As[r * 136 + c8] = v;
        }
    } else {
        const float* A = (const float*)Ain;
#pragma unroll
        for (int p = 0; p < 8; ++p) {
            int idx = tid + p * 512;
            int r = idx >> 5, cg = (idx & 31) * 4;
            int gr = rowBase + r;
            float4 v = make_float4(0.f, 0.f, 0.f, 0.f);
            if (gr < M) v = *(const float4*)(A + (size_t)gr * 128 + cg);
            st_bf4(&As[r * 136 + cg], v);
        }
    }
    load_weight(Bs, W, 128, tid);
    __syncthreads();

    HC acc[2][2];
    acc_zero(acc);
    mma_panel_h(As, 136, Bs, 136, acc, wr, wc, 8);
    __syncthreads();
    acc_store(S, acc, wr, wc);
    __syncthreads();

    if constexpr (MODE == 0) {
        for (int idx = tid; idx < 4096; idx += 512) {
            int r = idx >> 5, cq = (idx & 31) * 4;
            int gr = rowBase + r;
            if (gr < M) {
                float4 s = *(const float4*)&S[r * 132 + cq];
                s.x += bias[cq]; s.y += bias[cq + 1]; s.z += bias[cq + 2]; s.w += bias[cq + 3];
                *(float4*)(C + (size_t)gr * 128 + cq) = s;
            }
        }
    } else {
        __shared__ float muS[128], invS[128];
        for (int idx = tid; idx < 4096; idx += 512) {
            int r = idx >> 5, cq = (idx & 31) * 4;
            int gr = rowBase + r;
            if (gr < M) {
                float4 s = *(const float4*)&S[r * 132 + cq];
                float4 rr = *(const float4*)(resid + (size_t)gr * 128 + cq);
                s.x += bias[cq] + rr.x;     s.y += bias[cq + 1] + rr.y;
                s.z += bias[cq + 2] + rr.z; s.w += bias[cq + 3] + rr.w;
                *(float4*)&S[r * 132 + cq] = s;
            }
        }
        __syncthreads();
        if (tid < 128) {
            int gr = rowBase + tid;
            if (gr < M) {
                float s = 0.f, q2 = 0.f;
#pragma unroll 4
                for (int c = 0; c < 128; ++c) { float v = S[tid * 132 + c]; s += v; q2 += v * v; }
                float mean = s * (1.f / 128.f);
                float var = q2 * (1.f / 128.f) - mean * mean;
                muS[tid] = mean; invS[tid] = rsqrtf(var + 1e-5f);
            }
        }
        __syncthreads();
        for (int idx = tid; idx < 4096; idx += 512) {
            int r = idx >> 5, cq = (idx & 31) * 4;
            int gr = rowBase + r;
            if (gr < M) {
                float4 s = *(const float4*)&S[r * 132 + cq];
                float4 o;
                o.x = (s.x - muS[r]) * invS[r] * ln_g[cq]     + ln_b[cq];
                o.y = (s.y - muS[r]) * invS[r] * ln_g[cq + 1] + ln_b[cq + 1];
                o.z = (s.z - muS[r]) * invS[r] * ln_g[cq + 2] + ln_b[cq + 2];
                o.w = (s.w - muS[r]) * invS[r] * ln_g[cq + 3] + ln_b[cq + 3];
                *(float4*)(C + (size_t)gr * 128 + cq) = o;
            }
        }
    }
}

// ---------------- mega edge kernel: filter + k/v + scores ----------------------
__global__ __launch_bounds__(512)
void edge_fused_kernel(const float* __restrict__ f_ij, const float* __restrict__ r_ij,
                       const int* __restrict__ src, const int* __restrict__ dst,
                       const float* __restrict__ b_r1, const float* __restrict__ b_lin,
                       const float* __restrict__ b_r2,
                       const float* __restrict__ bk, const float* __restrict__ bv)
{
    extern __shared__ char smraw[];
    float* S  = (float*)smraw;                         // 128*132 f32   67584 B
    bf16*  Fs = (bf16*)(smraw + 67584);                // 128*72        18432 B
    bf16*  Ms = (bf16*)(smraw + 67584 + 18432);        // 128*136
    bf16*  Bs = (bf16*)(smraw + 67584 + 18432 + 34816);// 128*136
    __shared__ float Ce[128];
    __shared__ int   srcs[128], dsts[128];

    const int tid = threadIdx.x, wid = tid >> 5;
    const int wr = wid >> 2, wc = wid & 3;
    const int rowBase = blockIdx.x * 128;

#pragma unroll
    for (int p = 0; p < 4; ++p) {
        int idx = tid + p * 512;
        int r = idx >> 4, cg = (idx & 15) * 4;
        float4 v = *(const float4*)(f_ij + (size_t)(rowBase + r) * 64 + cg);
        st_bf4(&Fs[r * 72 + cg], v);
    }
    if (tid < 128) {
        int e = rowBase + tid;
        Ce[tid] = cutoff(r_ij[e]);
        srcs[tid] = src[e];
        dsts[tid] = dst[e];
    }

    HC acc[2][2];

    // ---- stage 1: U = ssp(f @ Wr1 + br1) ----
    acc_zero(acc);
    load_weight(Bs, g_Wr1h, 64, tid);
    __syncthreads();
    mma_panel_h(Fs, 72, Bs, 136, acc, wr, wc, 4);
    __syncthreads();
    acc_store(S, acc, wr, wc);
    __syncthreads();
    for (int idx = tid; idx < 4096; idx += 512) {
        int r = idx >> 5, cq = (idx & 31) * 4;
        float4 s = *(const float4*)&S[r * 132 + cq];
        float4 u;
        u.x = sspf(s.x + b_r1[cq]);     u.y = sspf(s.y + b_r1[cq + 1]);
        u.z = sspf(s.z + b_r1[cq + 2]); u.w = sspf(s.w + b_r1[cq + 3]);
        st_bf4(&Ms[r * 136 + cq], u);
    }

    // ---- stage 2: W = f@Wlin + U@Wr2 ----
    acc_zero(acc);
    load_weight(Bs, g_Wlinh, 64, tid);
    __syncthreads();
    mma_panel_h(Fs, 72, Bs, 136, acc, wr, wc, 4);
    __syncthreads();
    load_weight(Bs, g_Wr2h, 128, tid);
    __syncthreads();
    mma_panel_h(Ms, 136, Bs, 136, acc, wr, wc, 8);
    __syncthreads();
    acc_store(S, acc, wr, wc);
    __syncthreads();
    for (int idx = tid; idx < 4096; idx += 512) {
        int r = idx >> 5, cq = (idx & 31) * 4;
        float4 s = *(const float4*)&S[r * 132 + cq];
        uint2 hr = *(const uint2*)(g_hh + (size_t)srcs[r] * 128 + cq);
        float2 h0 = __bfloat1622float2(*(__nv_bfloat162*)&hr.x);
        float2 h1 = __bfloat1622float2(*(__nv_bfloat162*)&hr.y);
        float ce = Ce[r];
        float4 m;
        m.x = h0.x * (s.x + b_lin[cq]     + b_r2[cq])     * ce;
        m.y = h0.y * (s.y + b_lin[cq + 1] + b_r2[cq + 1]) * ce;
        m.z = h1.x * (s.z + b_lin[cq + 2] + b_r2[cq + 2]) * ce;
        m.w = h1.y * (s.w + b_lin[cq + 3] + b_r2[cq + 3]) * ce;
        st_bf4(&Ms[r * 136 + cq], m);
    }

    // ---- k stage: k = m@Wk, scores epilogue ----
    acc_zero(acc);
    load_weight(Bs, g_Wkh, 128, tid);
    __syncthreads();
    mma_panel_h(Ms, 136, Bs, 136, acc, wr, wc, 8);
    __syncthreads();
    acc_store(S, acc, wr, wc);
    __syncthreads();
    for (int t = tid; t < 1024; t += 512) {
        int r = t >> 3, h = t & 7;
        int d = dsts[r];
        const float* kp = &S[r * 132 + h * 16];
        const float4* qp = (const float4*)(g_q + (size_t)d * 128 + h * 16);
        const float* bb = bk + h * 16;
        float s = 0.f;
#pragma unroll
        for (int i = 0; i < 4; ++i) {
            float4 qv = qp[i];
            s += (kp[i * 4 + 0] + bb[i * 4 + 0]) * qv.x;
            s += (kp[i * 4 + 1] + bb[i * 4 + 1]) * qv.y;
            s += (kp[i * 4 + 2] + bb[i * 4 + 2]) * qv.z;
            s += (kp[i * 4 + 3] + bb[i * 4 + 3]) * qv.w;
        }
        s *= 0.25f;
        g_sc[(size_t)(rowBase + r) * NH + h] = s;
        atomicMax(&g_smax[d * NH + h], fenc(s));
    }

    // ---- v stage: v = m@Wv + bv -> bf16 ----
    acc_zero(acc);
    load_weight(Bs, g_Wvh, 128, tid);
    __syncthreads();
    mma_panel_h(Ms, 136, Bs, 136, acc, wr, wc, 8);
    __syncthreads();
    acc_store(S, acc, wr, wc);
    __syncthreads();
    for (int idx = tid; idx < 4096; idx += 512) {
        int r = idx >> 5, cq = (idx & 31) * 4;
        float4 s = *(const float4*)&S[r * 132 + cq];
        s.x += bv[cq]; s.y += bv[cq + 1]; s.z += bv[cq + 2]; s.w += bv[cq + 3];
        st_bf4(&g_vh[(size_t)(rowBase + r) * 128 + cq], s);
    }
}

// ---------------- gather aggregation: one warp per node ------------------------
__global__ __launch_bounds__(256)
void agg_kernel() {
    int w = (blockIdx.x * blockDim.x + threadIdx.x) >> 5;
    if (w >= NNODE) return;
    int l = threadIdx.x & 31;
    int c4 = l * 4;
    int h = l >> 2;
    float smax = fdec(g_smax[w * NH + h]);
    int o0 = g_off[w], o1 = g_off[w + 1];
    float a0 = 0.f, a1 = 0.f, a2 = 0.f, a3 = 0.f, den = 0.f;
    for (int i = o0; i < o1; ++i) {
        int e = g_eid[i];
        float ex = expf(g_sc[(size_t)e * NH + h] - smax);
        den += ex;
        uint2 raw = *(const uint2*)(g_vh + (size_t)e * 128 + c4);
        float2 v0 = __bfloat1622float2(*(__nv_bfloat162*)&raw.x);
        float2 v1 = __bfloat1622float2(*(__nv_bfloat162*)&raw.y);
        a0 += ex * v0.x; a1 += ex * v0.y; a2 += ex * v1.x; a3 += ex * v1.y;
    }
    float inv = 1.f / (den + 1e-16f);
    float4 o = make_float4(a0 * inv, a1 * inv, a2 * inv, a3 * inv);
    *(float4*)(g_agg + (size_t)w * 128 + c4) = o;
}

// ---------------- launch --------------------------------------------------------
extern "C" void kernel_launch(void* const* d_in, const int* in_sizes, int n_in,
                              void* d_out, int out_size) {
    const float* x     = (const float*)d_in[0];
    const float* t     = (const float*)d_in[1];
    const float* f_ij  = (const float*)d_in[2];
    const float* r_ij  = (const float*)d_in[3];
    const int*   src   = (const int*)d_in[4];
    const int*   dst   = (const int*)d_in[5];
    const float* W_lin = (const float*)d_in[6];
    const float* b_lin = (const float*)d_in[7];
    const float* W_r1  = (const float*)d_in[8];
    const float* b_r1  = (const float*)d_in[9];
    const float* W_r2  = (const float*)d_in[10];
    const float* b_r2  = (const float*)d_in[11];
    const float* Wq    = (const float*)d_in[12];
    const float* bq    = (const float*)d_in[13];
    const float* Wk    = (const float*)d_in[14];
    const float* bk    = (const float*)d_in[15];
    const float* Wv    = (const float*)d_in[16];
    const float* bv    = (const float*)d_in[17];
    const float* Wo    = (const float*)d_in[18];
    const float* bo    = (const float*)d_in[19];
    const float* ln_g  = (const float*)d_in[20];
    const float* ln_b  = (const float*)d_in[21];
    float* out = (float*)d_out;

    bf16 *pWr1h, *pWlinh, *pWr2h, *pWqh, *pWkh, *pWvh, *pWoh, *phh;
    float *pq, *pagg;
    cudaGetSymbolAddress((void**)&pWr1h, g_Wr1h);
    cudaGetSymbolAddress((void**)&pWlinh, g_Wlinh);
    cudaGetSymbolAddress((void**)&pWr2h, g_Wr2h);
    cudaGetSymbolAddress((void**)&pWqh, g_Wqh);
    cudaGetSymbolAddress((void**)&pWkh, g_Wkh);
    cudaGetSymbolAddress((void**)&pWvh, g_Wvh);
    cudaGetSymbolAddress((void**)&pWoh, g_Woh);
    cudaGetSymbolAddress((void**)&phh, g_hh);
    cudaGetSymbolAddress((void**)&pq,  g_q);
    cudaGetSymbolAddress((void**)&pagg, g_agg);

    const int SM_NODE = 128 * 132 * 4 + 2 * (128 * 136 * 2);
    const int SM_EDGE = 67584 + 18432 + 2 * 34816;
    cudaFuncSetAttribute((const void*)node_gemm_h<0, true>,  cudaFuncAttributeMaxDynamicSharedMemorySize, SM_NODE);
    cudaFuncSetAttribute((const void*)node_gemm_h<3, false>, cudaFuncAttributeMaxDynamicSharedMemorySize, SM_NODE);
    cudaFuncSetAttribute((const void*)edge_fused_kernel,     cudaFuncAttributeMaxDynamicSharedMemorySize, SM_EDGE);

    convert_kernel<<<16, 512>>>(W_r1, pWr1h, 64 * 128);
    convert_kernel<<<16, 512>>>(W_lin, pWlinh, 64 * 128);
    convert_kernel<<<32, 512>>>(W_r2, pWr2h, 128 * 128);
    convert_kernel<<<32, 512>>>(Wq, pWqh, 128 * 128);
    convert_kernel<<<32, 512>>>(Wk, pWkh, 128 * 128);
    convert_kernel<<<32, 512>>>(Wv, pWvh, 128 * 128);
    convert_kernel<<<32, 512>>>(Wo, pWoh, 128 * 128);

    const int TB = 256;
    int gridN  = (NNODE * Dm + TB - 1) / TB;
    int gridE  = (NEDGE + TB - 1) / TB;
    int gemmE  = NEDGE / 128;           // 5000
    int gemmN  = (NNODE + 127) / 128;   // 313

    init_kernel<<<gridN, TB>>>();
    add_h_kernel<<<gridN, TB>>>(x, t);

    // CSR build (independent of GEMM chain)
    hist_kernel<<<gridE, TB>>>(dst);
    scan_kernel<<<1, 1024>>>();
    idscatter_kernel<<<gridE, TB>>>(dst);

    // q = h @ Wq + bq
    node_gemm_h<0, true><<<gemmN, 512, SM_NODE>>>(phh, pWqh, bq, pq, NNODE,
                                                  nullptr, nullptr, nullptr);

    // fused filter + k/v + scores
    edge_fused_kernel<<<gemmE, 512, SM_EDGE>>>(f_ij, r_ij, src, dst,
                                               b_r1, b_lin, b_r2, bk, bv);

    // gather softmax + aggregation (no atomics)
    agg_kernel<<<(NNODE * 32 + TB - 1) / TB, TB>>>();

    // out = LN(x + agg @ Wo + bo)
    node_gemm_h<3, false><<<gemmN, 512, SM_NODE>>>(pagg, pWoh, bo, out, NNODE,
                                                   x, ln_g, ln_b);
}

// round 6
// speedup vs baseline: 2.4190x; 1.0434x over previous
#include <cuda_runtime.h>
#include <cuda_bf16.h>
#include <mma.h>
using namespace nvcuda;
typedef __nv_bfloat16 bf16;

#define Dm 128
#define NH 8
#define NNODE 40000
#define NEDGE 640000

// ---------------- scratch (static device globals) -----------------------------
__device__ bf16  g_hh[(size_t)NNODE * Dm];     // h = x+t, bf16
__device__ float g_q[(size_t)NNODE * Dm];      // queries fp32
__device__ bf16  g_vh[(size_t)NEDGE * Dm];     // values bf16
__device__ float g_sc[(size_t)NEDGE * NH];     // raw scores
__device__ unsigned g_smax[(size_t)NNODE * NH];
__device__ float g_agg[(size_t)NNODE * Dm];
// CSR build
__device__ int g_cnt[NNODE];
__device__ int g_cur[NNODE];
__device__ int g_off[NNODE + 1];
__device__ int g_eid[NEDGE];
// all bf16 weights in one buffer
#define OFF_WR1  0
#define OFF_WLIN 8192
#define OFF_WR2  16384
#define OFF_WQ   32768
#define OFF_WK   49152
#define OFF_WV   65536
#define OFF_WO   81920
#define W_TOTAL  98304
__device__ bf16 g_Wall[W_TOTAL];

// ---------------- helpers ------------------------------------------------------
__device__ __forceinline__ unsigned fenc(float f) {
    unsigned u = __float_as_uint(f);
    return (u & 0x80000000u) ? ~u : (u | 0x80000000u);
}
__device__ __forceinline__ float fdec(unsigned u) {
    return __uint_as_float((u & 0x80000000u) ? (u ^ 0x80000000u) : ~u);
}
#define SMAX_INIT 0x007fffffu

__device__ __forceinline__ float sspf(float v) {
    float sp = (v > 20.f) ? v : log1pf(expf(v));
    return sp - 0.6931471805599453f;
}
__device__ __forceinline__ float cutoff(float r) {
    float c = 0.5f * (cosf(r * 0.39269908169872414f) + 1.f);
    return (r < 8.f) ? c : 0.f;
}
__device__ __forceinline__ void st_bf4(bf16* p, float4 v) {
    __nv_bfloat162 a = __floats2bfloat162_rn(v.x, v.y);
    __nv_bfloat162 b = __floats2bfloat162_rn(v.z, v.w);
    uint2 u; u.x = *(unsigned*)&a; u.y = *(unsigned*)&b;
    *(uint2*)p = u;
}

// ---------------- convert all weights in one launch ----------------------------
__global__ void convert_all_kernel(const float* __restrict__ a0, const float* __restrict__ a1,
                                   const float* __restrict__ a2, const float* __restrict__ a3,
                                   const float* __restrict__ a4, const float* __restrict__ a5,
                                   const float* __restrict__ a6) {
    int i = blockIdx.x * blockDim.x + threadIdx.x;
    if (i >= W_TOTAL) return;
    const float* s; int rel;
    if      (i < 8192)  { s = a0; rel = i; }
    else if (i < 16384) { s = a1; rel = i - 8192; }
    else if (i < 32768) { s = a2; rel = i - 16384; }
    else if (i < 49152) { s = a3; rel = i - 32768; }
    else if (i < 65536) { s = a4; rel = i - 49152; }
    else if (i < 81920) { s = a5; rel = i - 65536; }
    else                { s = a6; rel = i - 81920; }
    g_Wall[i] = __float2bfloat16(s[rel]);
}
__global__ void init_kernel() {
    int gid = blockIdx.x * blockDim.x + threadIdx.x;
    if (gid < NNODE) { g_cnt[gid] = 0; g_cur[gid] = 0; }
    if (gid < NNODE * NH) g_smax[gid] = SMAX_INIT;
}
__global__ void add_h_kernel(const float* __restrict__ x, const float* __restrict__ t) {
    int gid = blockIdx.x * blockDim.x + threadIdx.x;
    if (gid < NNODE * Dm) g_hh[gid] = __float2bfloat16(x[gid] + t[gid]);
}

// ---------------- CSR build ----------------------------------------------------
__global__ void hist_kernel(const int* __restrict__ dst) {
    int e = blockIdx.x * blockDim.x + threadIdx.x;
    if (e < NEDGE) atomicAdd(&g_cnt[dst[e]], 1);
}
__global__ __launch_bounds__(1024) void scan_kernel() {
    __shared__ int part[1024];
    const int C = (NNODE + 1023) / 1024;
    int t = threadIdx.x;
    int base = t * C;
    int s = 0;
    for (int i = 0; i < C; ++i) {
        int idx = base + i;
        if (idx < NNODE) s += g_cnt[idx];
    }
    part[t] = s;
    __syncthreads();
    for (int d = 1; d < 1024; d <<= 1) {
        int v = (t >= d) ? part[t - d] : 0;
        __syncthreads();
        part[t] += v;
        __syncthreads();
    }
    int run = part[t] - s;
    for (int i = 0; i < C; ++i) {
        int idx = base + i;
        if (idx < NNODE) { g_off[idx] = run; run += g_cnt[idx]; }
    }
    if (t == 1023) g_off[NNODE] = run;
}
__global__ void idscatter_kernel(const int* __restrict__ dst) {
    int e = blockIdx.x * blockDim.x + threadIdx.x;
    if (e < NEDGE) {
        int d = dst[e];
        int p = g_off[d] + atomicAdd(&g_cur[d], 1);
        g_eid[p] = e;
    }
}

// ---------------- wmma bf16 machinery ------------------------------------------
typedef wmma::fragment<wmma::matrix_a, 16, 16, 16, bf16, wmma::row_major> HA;
typedef wmma::fragment<wmma::matrix_b, 16, 16, 16, bf16, wmma::row_major> HB;
typedef wmma::fragment<wmma::accumulator, 16, 16, 16, float> HC;

__device__ __forceinline__ void mma_panel_h(const bf16* As, int lda,
                                            const bf16* Bs, int ldb,
                                            HC (&acc)[2][2], int wr, int wc, int ksteps) {
    for (int kk = 0; kk < ksteps; ++kk) {
        HA a[2]; HB b[2];
#pragma unroll
        for (int i = 0; i < 2; ++i)
            wmma::load_matrix_sync(a[i], As + (size_t)(wr * 32 + i * 16) * lda + kk * 16, lda);
#pragma unroll
        for (int j = 0; j < 2; ++j)
            wmma::load_matrix_sync(b[j], Bs + (size_t)(kk * 16) * ldb + wc * 32 + j * 16, ldb);
#pragma unroll
        for (int i = 0; i < 2; ++i)
#pragma unroll
            for (int j = 0; j < 2; ++j) wmma::mma_sync(acc[i][j], a[i], b[j], acc[i][j]);
    }
}
__device__ __forceinline__ void acc_zero(HC (&acc)[2][2]) {
#pragma unroll
    for (int i = 0; i < 2; ++i)
#pragma unroll
        for (int j = 0; j < 2; ++j) wmma::fill_fragment(acc[i][j], 0.f);
}
__device__ __forceinline__ void acc_store(float* S, HC (&acc)[2][2], int wr, int wc) {
#pragma unroll
    for (int i = 0; i < 2; ++i)
#pragma unroll
        for (int j = 0; j < 2; ++j)
            wmma::store_matrix_sync(S + (size_t)(wr * 32 + i * 16) * 132 + wc * 32 + j * 16,
                                    acc[i][j], 132, wmma::mem_row_major);
}
// 256-thread weight loader into Bs (LDB=136)
__device__ __forceinline__ void load_weight256(bf16* Bs, const bf16* W, int rows, int tid) {
    int n = rows * 16;
    for (int idx = tid; idx < n; idx += 256) {
        int r = idx >> 4, c8 = (idx & 15) * 8;
        *(uint4*)&Bs[r * 136 + c8] = *(const uint4*)(W + (size_t)r * 128 + c8);
    }
}
// 512-thread weight loader
__device__ __forceinline__ void load_weight512(bf16* Bs, const bf16* W, int rows, int tid) {
    int n = rows * 16;
    for (int idx = tid; idx < n; idx += 512) {
        int r = idx >> 4, c8 = (idx & 15) * 8;
        *(uint4*)&Bs[r * 136 + c8] = *(const uint4*)(W + (size_t)r * 128 + c8);
    }
}

// ---------------- node GEMM: MODE 0 = +bias; MODE 3 = resid+LN -----------------
template <int MODE, bool AB16>
__global__ __launch_bounds__(512)
void node_gemm_h(const void* __restrict__ Ain, const bf16* __restrict__ W,
                 const float* __restrict__ bias, float* __restrict__ C, int M,
                 const float* __restrict__ resid,
                 const float* __restrict__ ln_g, const float* __restrict__ ln_b)
{
    extern __shared__ char smraw[];
    float* S  = (float*)smraw;                        // 128*132 f32
    bf16*  As = (bf16*)(smraw + 128 * 132 * 4);       // 128*136
    bf16*  Bs = As + 128 * 136;                       // 128*136
    const int tid = threadIdx.x, wid = tid >> 5;
    const int wr = wid >> 2, wc = wid & 3;
    const int rowBase = blockIdx.x * 128;

    if constexpr (AB16) {
        const bf16* A = (const bf16*)Ain;
#pragma unroll
        for (int p = 0; p < 4; ++p) {
            int idx = tid + p * 512;
            int r = idx >> 4, c8 = (idx & 15) * 8;
            int gr = rowBase + r;
            uint4 v = make_uint4(0, 0, 0, 0);
            if (gr < M) v = *(const uint4*)(A + (size_t)gr * 128 + c8);
            *(uint4*)&As[r * 136 + c8] = v;
        }
    } else {
        const float* A = (const float*)Ain;
#pragma unroll
        for (int p = 0; p < 8; ++p) {
            int idx = tid + p * 512;
            int r = idx >> 5, cg = (idx & 31) * 4;
            int gr = rowBase + r;
            float4 v = make_float4(0.f, 0.f, 0.f, 0.f);
            if (gr < M) v = *(const float4*)(A + (size_t)gr * 128 + cg);
            st_bf4(&As[r * 136 + cg], v);
        }
    }
    load_weight512(Bs, W, 128, tid);
    __syncthreads();

    HC acc[2][2];
    acc_zero(acc);
    mma_panel_h(As, 136, Bs, 136, acc, wr, wc, 8);
    __syncthreads();
    acc_store(S, acc, wr, wc);
    __syncthreads();

    if constexpr (MODE == 0) {
        for (int idx = tid; idx < 4096; idx += 512) {
            int r = idx >> 5, cq = (idx & 31) * 4;
            int gr = rowBase + r;
            if (gr < M) {
                float4 s = *(const float4*)&S[r * 132 + cq];
                s.x += bias[cq]; s.y += bias[cq + 1]; s.z += bias[cq + 2]; s.w += bias[cq + 3];
                *(float4*)(C + (size_t)gr * 128 + cq) = s;
            }
        }
    } else {
        __shared__ float muS[128], invS[128];
        for (int idx = tid; idx < 4096; idx += 512) {
            int r = idx >> 5, cq = (idx & 31) * 4;
            int gr = rowBase + r;
            if (gr < M) {
                float4 s = *(const float4*)&S[r * 132 + cq];
                float4 rr = *(const float4*)(resid + (size_t)gr * 128 + cq);
                s.x += bias[cq] + rr.x;     s.y += bias[cq + 1] + rr.y;
                s.z += bias[cq + 2] + rr.z; s.w += bias[cq + 3] + rr.w;
                *(float4*)&S[r * 132 + cq] = s;
            }
        }
        __syncthreads();
        if (tid < 128) {
            int gr = rowBase + tid;
            if (gr < M) {
                float s = 0.f, q2 = 0.f;
#pragma unroll 4
                for (int c = 0; c < 128; ++c) { float v = S[tid * 132 + c]; s += v; q2 += v * v; }
                float mean = s * (1.f / 128.f);
                float var = q2 * (1.f / 128.f) - mean * mean;
                muS[tid] = mean; invS[tid] = rsqrtf(var + 1e-5f);
            }
        }
        __syncthreads();
        for (int idx = tid; idx < 4096; idx += 512) {
            int r = idx >> 5, cq = (idx & 31) * 4;
            int gr = rowBase + r;
            if (gr < M) {
                float4 s = *(const float4*)&S[r * 132 + cq];
                float4 o;
                o.x = (s.x - muS[r]) * invS[r] * ln_g[cq]     + ln_b[cq];
                o.y = (s.y - muS[r]) * invS[r] * ln_g[cq + 1] + ln_b[cq + 1];
                o.z = (s.z - muS[r]) * invS[r] * ln_g[cq + 2] + ln_b[cq + 2];
                o.w = (s.w - muS[r]) * invS[r] * ln_g[cq + 3] + ln_b[cq + 3];
                *(float4*)(C + (size_t)gr * 128 + cq) = o;
            }
        }
    }
}

// ---------------- mega edge kernel (BM=64, 256 thr, 2 CTAs/SM) -----------------
// per 64-edge tile: U = ssp(f@Wr1+br1); m = hh[src]*(f@Wlin + U@Wr2 + b)*C(r)
// k = m@Wk (+bk) -> scores + atomicMax;  v = m@Wv + bv -> g_vh
#define SME_S   0
#define SME_F   33792
#define SME_M   43008
#define SME_B   60416
#define SME_TOT 95232
__global__ __launch_bounds__(256)
void edge_fused_kernel(const float* __restrict__ f_ij, const float* __restrict__ r_ij,
                       const int* __restrict__ src, const int* __restrict__ dst,
                       const float* __restrict__ b_r1, const float* __restrict__ b_lin,
                       const float* __restrict__ b_r2,
                       const float* __restrict__ bk, const float* __restrict__ bv)
{
    extern __shared__ char smraw[];
    float* S  = (float*)(smraw + SME_S);     // 64*132 f32
    bf16*  Fs = (bf16*)(smraw + SME_F);      // 64*72
    bf16*  Ms = (bf16*)(smraw + SME_M);      // 64*136
    bf16*  Bs = (bf16*)(smraw + SME_B);      // 128*136
    __shared__ float Ce[64];
    __shared__ int   srcs[64], dsts[64];

    const int tid = threadIdx.x, wid = tid >> 5;
    const int wr = wid >> 2, wc = wid & 3;         // 2 x 4 warp grid
    const int rowBase = blockIdx.x * 64;           // NEDGE = 10000*64 exactly

    // f tile: 64 x 64 fp32 -> bf16 (1024 float4)
#pragma unroll
    for (int p = 0; p < 4; ++p) {
        int idx = tid + p * 256;
        int r = idx >> 4, cg = (idx & 15) * 4;
        float4 v = *(const float4*)(f_ij + (size_t)(rowBase + r) * 64 + cg);
        st_bf4(&Fs[r * 72 + cg], v);
    }
    if (tid < 64) {
        int e = rowBase + tid;
        Ce[tid] = cutoff(r_ij[e]);
        srcs[tid] = src[e];
        dsts[tid] = dst[e];
    }

    HC acc[2][2];

    // ---- stage 1: U = ssp(f @ Wr1 + br1) ----
    acc_zero(acc);
    load_weight256(Bs, g_Wall + OFF_WR1, 64, tid);
    __syncthreads();
    mma_panel_h(Fs, 72, Bs, 136, acc, wr, wc, 4);
    __syncthreads();
    acc_store(S, acc, wr, wc);
    __syncthreads();
    for (int idx = tid; idx < 2048; idx += 256) {
        int r = idx >> 5, cq = (idx & 31) * 4;
        float4 s = *(const float4*)&S[r * 132 + cq];
        float4 u;
        u.x = sspf(s.x + b_r1[cq]);     u.y = sspf(s.y + b_r1[cq + 1]);
        u.z = sspf(s.z + b_r1[cq + 2]); u.w = sspf(s.w + b_r1[cq + 3]);
        st_bf4(&Ms[r * 136 + cq], u);
    }

    // ---- stage 2: W = f@Wlin + U@Wr2; m epilogue ----
    acc_zero(acc);
    load_weight256(Bs, g_Wall + OFF_WLIN, 64, tid);
    __syncthreads();
    mma_panel_h(Fs, 72, Bs, 136, acc, wr, wc, 4);
    __syncthreads();
    load_weight256(Bs, g_Wall + OFF_WR2, 128, tid);
    __syncthreads();
    mma_panel_h(Ms, 136, Bs, 136, acc, wr, wc, 8);
    __syncthreads();
    acc_store(S, acc, wr, wc);
    __syncthreads();
    for (int idx = tid; idx < 2048; idx += 256) {
        int r = idx >> 5, cq = (idx & 31) * 4;
        float4 s = *(const float4*)&S[r * 132 + cq];
        uint2 hr = *(const uint2*)(g_hh + (size_t)srcs[r] * 128 + cq);
        float2 h0 = __bfloat1622float2(*(__nv_bfloat162*)&hr.x);
        float2 h1 = __bfloat1622float2(*(__nv_bfloat162*)&hr.y);
        float ce = Ce[r];
        float4 m;
        m.x = h0.x * (s.x + b_lin[cq]     + b_r2[cq])     * ce;
        m.y = h0.y * (s.y + b_lin[cq + 1] + b_r2[cq + 1]) * ce;
        m.z = h1.x * (s.z + b_lin[cq + 2] + b_r2[cq + 2]) * ce;
        m.w = h1.y * (s.w + b_lin[cq + 3] + b_r2[cq + 3]) * ce;
        st_bf4(&Ms[r * 136 + cq], m);
    }

    // ---- k stage: k = m@Wk, scores epilogue ----
    acc_zero(acc);
    load_weight256(Bs, g_Wall + OFF_WK, 128, tid);
    __syncthreads();
    mma_panel_h(Ms, 136, Bs, 136, acc, wr, wc, 8);
    __syncthreads();
    acc_store(S, acc, wr, wc);
    __syncthreads();
    for (int t = tid; t < 512; t += 256) {
        int r = t >> 3, h = t & 7;
        int d = dsts[r];
        const float* kp = &S[r * 132 + h * 16];
        const float4* qp = (const float4*)(g_q + (size_t)d * 128 + h * 16);
        const float* bb = bk + h * 16;
        float s = 0.f;
#pragma unroll
        for (int i = 0; i < 4; ++i) {
            float4 qv = qp[i];
            s += (kp[i * 4 + 0] + bb[i * 4 + 0]) * qv.x;
            s += (kp[i * 4 + 1] + bb[i * 4 + 1]) * qv.y;
            s += (kp[i * 4 + 2] + bb[i * 4 + 2]) * qv.z;
            s += (kp[i * 4 + 3] + bb[i * 4 + 3]) * qv.w;
        }
        s *= 0.25f;
        g_sc[(size_t)(rowBase + r) * NH + h] = s;
        atomicMax(&g_smax[d * NH + h], fenc(s));
    }

    // ---- v stage: v = m@Wv + bv -> bf16 ----
    acc_zero(acc);
    load_weight256(Bs, g_Wall + OFF_WV, 128, tid);
    __syncthreads();
    mma_panel_h(Ms, 136, Bs, 136, acc, wr, wc, 8);
    __syncthreads();
    acc_store(S, acc, wr, wc);
    __syncthreads();
    for (int idx = tid; idx < 2048; idx += 256) {
        int r = idx >> 5, cq = (idx & 31) * 4;
        float4 s = *(const float4*)&S[r * 132 + cq];
        s.x += bv[cq]; s.y += bv[cq + 1]; s.z += bv[cq + 2]; s.w += bv[cq + 3];
        st_bf4(&g_vh[(size_t)(rowBase + r) * 128 + cq], s);
    }
}

// ---------------- gather aggregation: one warp per node ------------------------
__global__ __launch_bounds__(256)
void agg_kernel() {
    int w = (blockIdx.x * blockDim.x + threadIdx.x) >> 5;
    if (w >= NNODE) return;
    int l = threadIdx.x & 31;
    int c4 = l * 4;
    int h = l >> 2;
    float smax = fdec(g_smax[w * NH + h]);
    int o0 = g_off[w], o1 = g_off[w + 1];
    float a0 = 0.f, a1 = 0.f, a2 = 0.f, a3 = 0.f, den = 0.f;
    for (int i = o0; i < o1; ++i) {
        int e = g_eid[i];
        float ex = expf(g_sc[(size_t)e * NH + h] - smax);
        den += ex;
        uint2 raw = *(const uint2*)(g_vh + (size_t)e * 128 + c4);
        float2 v0 = __bfloat1622float2(*(__nv_bfloat162*)&raw.x);
        float2 v1 = __bfloat1622float2(*(__nv_bfloat162*)&raw.y);
        a0 += ex * v0.x; a1 += ex * v0.y; a2 += ex * v1.x; a3 += ex * v1.y;
    }
    float inv = 1.f / (den + 1e-16f);
    float4 o = make_float4(a0 * inv, a1 * inv, a2 * inv, a3 * inv);
    *(float4*)(g_agg + (size_t)w * 128 + c4) = o;
}

// ---------------- launch --------------------------------------------------------
extern "C" void kernel_launch(void* const* d_in, const int* in_sizes, int n_in,
                              void* d_out, int out_size) {
    const float* x     = (const float*)d_in[0];
    const float* t     = (const float*)d_in[1];
    const float* f_ij  = (const float*)d_in[2];
    const float* r_ij  = (const float*)d_in[3];
    const int*   src   = (const int*)d_in[4];
    const int*   dst   = (const int*)d_in[5];
    const float* W_lin = (const float*)d_in[6];
    const float* b_lin = (const float*)d_in[7];
    const float* W_r1  = (const float*)d_in[8];
    const float* b_r1  = (const float*)d_in[9];
    const float* W_r2  = (const float*)d_in[10];
    const float* b_r2  = (const float*)d_in[11];
    const float* Wq    = (const float*)d_in[12];
    const float* bq    = (const float*)d_in[13];
    const float* Wk    = (const float*)d_in[14];
    const float* bk    = (const float*)d_in[15];
    const float* Wv    = (const float*)d_in[16];
    const float* bv    = (const float*)d_in[17];
    const float* Wo    = (const float*)d_in[18];
    const float* bo    = (const float*)d_in[19];
    const float* ln_g  = (const float*)d_in[20];
    const float* ln_b  = (const float*)d_in[21];
    float* out = (float*)d_out;

    bf16 *pWall, *phh;
    float *pq, *pagg;
    cudaGetSymbolAddress((void**)&pWall, g_Wall);
    cudaGetSymbolAddress((void**)&phh, g_hh);
    cudaGetSymbolAddress((void**)&pq,  g_q);
    cudaGetSymbolAddress((void**)&pagg, g_agg);

    const int SM_NODE = 128 * 132 * 4 + 2 * (128 * 136 * 2);
    cudaFuncSetAttribute((const void*)node_gemm_h<0, true>,  cudaFuncAttributeMaxDynamicSharedMemorySize, SM_NODE);
    cudaFuncSetAttribute((const void*)node_gemm_h<3, false>, cudaFuncAttributeMaxDynamicSharedMemorySize, SM_NODE);
    cudaFuncSetAttribute((const void*)edge_fused_kernel,     cudaFuncAttributeMaxDynamicSharedMemorySize, SME_TOT);

    const int TB = 256;
    int gridN  = (NNODE * Dm + TB - 1) / TB;
    int gridE  = (NEDGE + TB - 1) / TB;
    int gemmE  = NEDGE / 64;            // 10000
    int gemmN  = (NNODE + 127) / 128;   // 313

    // launch order chosen so ncu (-s 5 -c 1) captures edge_fused_kernel
    convert_all_kernel<<<W_TOTAL / 512, 512>>>(W_r1, W_lin, W_r2, Wq, Wk, Wv, Wo); // 0
    init_kernel<<<gridN, TB>>>();                                                   // 1
    add_h_kernel<<<gridN, TB>>>(x, t);                                              // 2
    node_gemm_h<0, true><<<gemmN, 512, SM_NODE>>>(phh, pWall + OFF_WQ, bq, pq,      // 3
                                                  NNODE, nullptr, nullptr, nullptr);
    hist_kernel<<<gridE, TB>>>(dst);                                                // 4
    edge_fused_kernel<<<gemmE, 256, SME_TOT>>>(f_ij, r_ij, src, dst,                // 5 <- profiled
                                               b_r1, b_lin, b_r2, bk, bv);
    scan_kernel<<<1, 1024>>>();                                                     // 6
    idscatter_kernel<<<gridE, TB>>>(dst);                                           // 7
    agg_kernel<<<(NNODE * 32 + TB - 1) / TB, TB>>>();                               // 8
    node_gemm_h<3, false><<<gemmN, 512, SM_NODE>>>(pagg, pWall + OFF_WO, bo, out,   // 9
                                                   NNODE, x, ln_g, ln_b);
}

// round 7
// speedup vs baseline: 2.8654x; 1.1846x over previous
#include <cuda_runtime.h>
#include <cuda_bf16.h>
#include <mma.h>
using namespace nvcuda;
typedef __nv_bfloat16 bf16;

#define Dm 128
#define NH 8
#define NNODE 40000
#define NEDGE 640000

// ---------------- scratch (static device globals) -----------------------------
__device__ bf16  g_hh[(size_t)NNODE * Dm];     // h = x+t, bf16
__device__ float g_q[(size_t)NNODE * Dm];      // queries fp32
__device__ bf16  g_vh[(size_t)NEDGE * Dm];     // values bf16
__device__ float g_sc[(size_t)NEDGE * NH];     // raw scores
__device__ unsigned g_smax[(size_t)NNODE * NH];
__device__ float g_agg[(size_t)NNODE * Dm];
// CSR build
__device__ int g_cnt[NNODE];
__device__ int g_cur[NNODE];
__device__ int g_off[NNODE + 1];
__device__ int g_eid[NEDGE];
// all bf16 weights in one buffer
#define OFF_WR1  0
#define OFF_WLIN 8192
#define OFF_WR2  16384
#define OFF_WQ   32768
#define OFF_WK   49152
#define OFF_WV   65536
#define OFF_WO   81920
#define W_TOTAL  98304
__device__ bf16 g_Wall[W_TOTAL];

// ---------------- helpers ------------------------------------------------------
__device__ __forceinline__ unsigned fenc(float f) {
    unsigned u = __float_as_uint(f);
    return (u & 0x80000000u) ? ~u : (u | 0x80000000u);
}
__device__ __forceinline__ float fdec(unsigned u) {
    return __uint_as_float((u & 0x80000000u) ? (u ^ 0x80000000u) : ~u);
}
#define SMAX_INIT 0x007fffffu

// branch-free shifted softplus: ln2*log2(1+2^(v/ln2)) - ln2
// valid for |v| < ~80 (here |v| <= ~9); abs err ~1e-6
__device__ __forceinline__ float sspf(float v) {
    float t, l;
    asm("ex2.approx.f32 %0, %1;" : "=f"(t) : "f"(v * 1.4426950408889634f));
    asm("lg2.approx.f32 %0, %1;" : "=f"(l) : "f"(1.0f + t));
    return fmaf(0.6931471805599453f, l, -0.6931471805599453f);
}
__device__ __forceinline__ float cutoff(float r) {
    float c = 0.5f * (cosf(r * 0.39269908169872414f) + 1.f);
    return (r < 8.f) ? c : 0.f;
}
__device__ __forceinline__ void st_bf4(bf16* p, float4 v) {
    __nv_bfloat162 a = __floats2bfloat162_rn(v.x, v.y);
    __nv_bfloat162 b = __floats2bfloat162_rn(v.z, v.w);
    uint2 u; u.x = *(unsigned*)&a; u.y = *(unsigned*)&b;
    *(uint2*)p = u;
}

// ---------------- convert all weights in one launch ----------------------------
__global__ void convert_all_kernel(const float* __restrict__ a0, const float* __restrict__ a1,
                                   const float* __restrict__ a2, const float* __restrict__ a3,
                                   const float* __restrict__ a4, const float* __restrict__ a5,
                                   const float* __restrict__ a6) {
    int i = blockIdx.x * blockDim.x + threadIdx.x;
    if (i >= W_TOTAL) return;
    const float* s; int rel;
    if      (i < 8192)  { s = a0; rel = i; }
    else if (i < 16384) { s = a1; rel = i - 8192; }
    else if (i < 32768) { s = a2; rel = i - 16384; }
    else if (i < 49152) { s = a3; rel = i - 32768; }
    else if (i < 65536) { s = a4; rel = i - 49152; }
    else if (i < 81920) { s = a5; rel = i - 65536; }
    else                { s = a6; rel = i - 81920; }
    g_Wall[i] = __float2bfloat16(s[rel]);
}
__global__ void init_kernel() {
    int gid = blockIdx.x * blockDim.x + threadIdx.x;
    if (gid < NNODE) { g_cnt[gid] = 0; g_cur[gid] = 0; }
    if (gid < NNODE * NH) g_smax[gid] = SMAX_INIT;
}
__global__ void add_h_kernel(const float* __restrict__ x, const float* __restrict__ t) {
    int gid = blockIdx.x * blockDim.x + threadIdx.x;
    if (gid < NNODE * Dm) g_hh[gid] = __float2bfloat16(x[gid] + t[gid]);
}

// ---------------- CSR build ----------------------------------------------------
__global__ void hist_kernel(const int* __restrict__ dst) {
    int e = blockIdx.x * blockDim.x + threadIdx.x;
    if (e < NEDGE) atomicAdd(&g_cnt[dst[e]], 1);
}
__global__ __launch_bounds__(1024) void scan_kernel() {
    __shared__ int part[1024];
    const int C = (NNODE + 1023) / 1024;
    int t = threadIdx.x;
    int base = t * C;
    int s = 0;
    for (int i = 0; i < C; ++i) {
        int idx = base + i;
        if (idx < NNODE) s += g_cnt[idx];
    }
    part[t] = s;
    __syncthreads();
    for (int d = 1; d < 1024; d <<= 1) {
        int v = (t >= d) ? part[t - d] : 0;
        __syncthreads();
        part[t] += v;
        __syncthreads();
    }
    int run = part[t] - s;
    for (int i = 0; i < C; ++i) {
        int idx = base + i;
        if (idx < NNODE) { g_off[idx] = run; run += g_cnt[idx]; }
    }
    if (t == 1023) g_off[NNODE] = run;
}
__global__ void idscatter_kernel(const int* __restrict__ dst) {
    int e = blockIdx.x * blockDim.x + threadIdx.x;
    if (e < NEDGE) {
        int d = dst[e];
        int p = g_off[d] + atomicAdd(&g_cur[d], 1);
        g_eid[p] = e;
    }
}

// ---------------- wmma bf16 machinery ------------------------------------------
typedef wmma::fragment<wmma::matrix_a, 16, 16, 16, bf16, wmma::row_major> HA;
typedef wmma::fragment<wmma::matrix_b, 16, 16, 16, bf16, wmma::row_major> HB;
typedef wmma::fragment<wmma::accumulator, 16, 16, 16, float> HC;

__device__ __forceinline__ void mma_panel_h(const bf16* As, int lda,
                                            const bf16* Bs, int ldb,
                                            HC (&acc)[2][2], int wr, int wc, int ksteps) {
    for (int kk = 0; kk < ksteps; ++kk) {
        HA a[2]; HB b[2];
#pragma unroll
        for (int i = 0; i < 2; ++i)
            wmma::load_matrix_sync(a[i], As + (size_t)(wr * 32 + i * 16) * lda + kk * 16, lda);
#pragma unroll
        for (int j = 0; j < 2; ++j)
            wmma::load_matrix_sync(b[j], Bs + (size_t)(kk * 16) * ldb + wc * 32 + j * 16, ldb);
#pragma unroll
        for (int i = 0; i < 2; ++i)
#pragma unroll
            for (int j = 0; j < 2; ++j) wmma::mma_sync(acc[i][j], a[i], b[j], acc[i][j]);
    }
}
__device__ __forceinline__ void acc_zero(HC (&acc)[2][2]) {
#pragma unroll
    for (int i = 0; i < 2; ++i)
#pragma unroll
        for (int j = 0; j < 2; ++j) wmma::fill_fragment(acc[i][j], 0.f);
}
__device__ __forceinline__ void acc_store(float* S, HC (&acc)[2][2], int wr, int wc) {
#pragma unroll
    for (int i = 0; i < 2; ++i)
#pragma unroll
        for (int j = 0; j < 2; ++j)
            wmma::store_matrix_sync(S + (size_t)(wr * 32 + i * 16) * 132 + wc * 32 + j * 16,
                                    acc[i][j], 132, wmma::mem_row_major);
}
// store a warp's 32x32 acc into a 64-row half buffer; wrl = wr&1
__device__ __forceinline__ void acc_store_half(float* S, HC (&acc)[2][2], int wrl, int wc) {
#pragma unroll
    for (int i = 0; i < 2; ++i)
#pragma unroll
        for (int j = 0; j < 2; ++j)
            wmma::store_matrix_sync(S + (size_t)(wrl * 32 + i * 16) * 132 + wc * 32 + j * 16,
                                    acc[i][j], 132, wmma::mem_row_major);
}
// 512-thread weight loader into Bs (LDB=136)
__device__ __forceinline__ void load_weight512(bf16* Bs, const bf16* W, int rows, int tid) {
    int n = rows * 16;
    for (int idx = tid; idx < n; idx += 512) {
        int r = idx >> 4, c8 = (idx & 15) * 8;
        *(uint4*)&Bs[r * 136 + c8] = *(const uint4*)(W + (size_t)r * 128 + c8);
    }
}

// ---------------- node GEMM: MODE 0 = +bias; MODE 3 = resid+LN -----------------
template <int MODE, bool AB16>
__global__ __launch_bounds__(512)
void node_gemm_h(const void* __restrict__ Ain, const bf16* __restrict__ W,
                 const float* __restrict__ bias, float* __restrict__ C, int M,
                 const float* __restrict__ resid,
                 const float* __restrict__ ln_g, const float* __restrict__ ln_b)
{
    extern __shared__ char smraw[];
    float* S  = (float*)smraw;                        // 128*132 f32
    bf16*  As = (bf16*)(smraw + 128 * 132 * 4);       // 128*136
    bf16*  Bs = As + 128 * 136;                       // 128*136
    const int tid = threadIdx.x, wid = tid >> 5;
    const int wr = wid >> 2, wc = wid & 3;
    const int rowBase = blockIdx.x * 128;

    if constexpr (AB16) {
        const bf16* A = (const bf16*)Ain;
#pragma unroll
        for (int p = 0; p < 4; ++p) {
            int idx = tid + p * 512;
            int r = idx >> 4, c8 = (idx & 15) * 8;
            int gr = rowBase + r;
            uint4 v = make_uint4(0, 0, 0, 0);
            if (gr < M) v = *(const uint4*)(A + (size_t)gr * 128 + c8);
            *(uint4*)&As[r * 136 + c8] = v;
        }
    } else {
        const float* A = (const float*)Ain;
#pragma unroll
        for (int p = 0; p < 8; ++p) {
            int idx = tid + p * 512;
            int r = idx >> 5, cg = (idx & 31) * 4;
            int gr = rowBase + r;
            float4 v = make_float4(0.f, 0.f, 0.f, 0.f);
            if (gr < M) v = *(const float4*)(A + (size_t)gr * 128 + cg);
            st_bf4(&As[r * 136 + cg], v);
        }
    }
    load_weight512(Bs, W, 128, tid);
    __syncthreads();

    HC acc[2][2];
    acc_zero(acc);
    mma_panel_h(As, 136, Bs, 136, acc, wr, wc, 8);
    __syncthreads();
    acc_store(S, acc, wr, wc);
    __syncthreads();

    if constexpr (MODE == 0) {
        for (int idx = tid; idx < 4096; idx += 512) {
            int r = idx >> 5, cq = (idx & 31) * 4;
            int gr = rowBase + r;
            if (gr < M) {
                float4 s = *(const float4*)&S[r * 132 + cq];
                s.x += bias[cq]; s.y += bias[cq + 1]; s.z += bias[cq + 2]; s.w += bias[cq + 3];
                *(float4*)(C + (size_t)gr * 128 + cq) = s;
            }
        }
    } else {
        __shared__ float muS[128], invS[128];
        for (int idx = tid; idx < 4096; idx += 512) {
            int r = idx >> 5, cq = (idx & 31) * 4;
            int gr = rowBase + r;
            if (gr < M) {
                float4 s = *(const float4*)&S[r * 132 + cq];
                float4 rr = *(const float4*)(resid + (size_t)gr * 128 + cq);
                s.x += bias[cq] + rr.x;     s.y += bias[cq + 1] + rr.y;
                s.z += bias[cq + 2] + rr.z; s.w += bias[cq + 3] + rr.w;
                *(float4*)&S[r * 132 + cq] = s;
            }
        }
        __syncthreads();
        if (tid < 128) {
            int gr = rowBase + tid;
            if (gr < M) {
                float s = 0.f, q2 = 0.f;
#pragma unroll 4
                for (int c = 0; c < 128; ++c) { float v = S[tid * 132 + c]; s += v; q2 += v * v; }
                float mean = s * (1.f / 128.f);
                float var = q2 * (1.f / 128.f) - mean * mean;
                muS[tid] = mean; invS[tid] = rsqrtf(var + 1e-5f);
            }
        }
        __syncthreads();
        for (int idx = tid; idx < 4096; idx += 512) {
            int r = idx >> 5, cq = (idx & 31) * 4;
            int gr = rowBase + r;
            if (gr < M) {
                float4 s = *(const float4*)&S[r * 132 + cq];
                float4 o;
                o.x = (s.x - muS[r]) * invS[r] * ln_g[cq]     + ln_b[cq];
                o.y = (s.y - muS[r]) * invS[r] * ln_g[cq + 1] + ln_b[cq + 1];
                o.z = (s.z - muS[r]) * invS[r] * ln_g[cq + 2] + ln_b[cq + 2];
                o.w = (s.w - muS[r]) * invS[r] * ln_g[cq + 3] + ln_b[cq + 3];
                *(float4*)(C + (size_t)gr * 128 + cq) = o;
            }
        }
    }
}

// ---------------- mega edge kernel (BM=128, 512 thr, 2 CTAs/SM = 32 warps) -----
// smem: S half-staging (64x132 f32), F (128x72 bf16), Ms (128x136 bf16),
//       Bs half-weight (64x136 bf16)  -> 104448 B dynamic
#define SMO_S 0
#define SMO_F 33792
#define SMO_M 52224
#define SMO_B 87040
#define SMO_TOT 104448
__global__ __launch_bounds__(512, 2)
void edge_fused_kernel(const float* __restrict__ f_ij, const float* __restrict__ r_ij,
                       const int* __restrict__ src, const int* __restrict__ dst,
                       const float* __restrict__ b_r1, const float* __restrict__ b_lin,
                       const float* __restrict__ b_r2,
                       const float* __restrict__ bk, const float* __restrict__ bv)
{
    extern __shared__ char smraw[];
    float* S  = (float*)(smraw + SMO_S);     // 64*132 f32 (half staging)
    bf16*  Fs = (bf16*)(smraw + SMO_F);      // 128*72
    bf16*  Ms = (bf16*)(smraw + SMO_M);      // 128*136
    bf16*  Bs = (bf16*)(smraw + SMO_B);      // 64*136 (half weight)
    __shared__ float Ce[128];
    __shared__ int   srcs[128], dsts[128];

    const int tid = threadIdx.x, wid = tid >> 5;
    const int wr = wid >> 2, wc = wid & 3;          // 4x4 warp grid, warp tile 32x32
    const int rowBase = blockIdx.x * 128;           // NEDGE = 5000*128 exactly

    // f tile: 128 x 64 fp32 -> bf16 (2048 float4)
#pragma unroll
    for (int p = 0; p < 4; ++p) {
        int idx = tid + p * 512;
        int r = idx >> 4, cg = (idx & 15) * 4;
        float4 v = *(const float4*)(f_ij + (size_t)(rowBase + r) * 64 + cg);
        st_bf4(&Fs[r * 72 + cg], v);
    }
    if (tid < 128) {
        int e = rowBase + tid;
        Ce[tid] = cutoff(r_ij[e]);
        srcs[tid] = src[e];
        dsts[tid] = dst[e];
    }

    HC acc[2][2];

    // ---- stage 1: U = ssp(f @ Wr1 + br1) -> Ms ----
    acc_zero(acc);
    load_weight512(Bs, g_Wall + OFF_WR1, 64, tid);
    __syncthreads();
    mma_panel_h(Fs, 72, Bs, 136, acc, wr, wc, 4);
    __syncthreads();
#pragma unroll
    for (int hh = 0; hh < 2; ++hh) {
        if ((wr >> 1) == hh) acc_store_half(S, acc, wr & 1, wc);
        __syncthreads();
#pragma unroll
        for (int p = 0; p < 4; ++p) {
            int idx = tid + p * 512;
            int r = idx >> 5, cq = (idx & 31) * 4;
            float4 s = *(const float4*)&S[r * 132 + cq];
            float4 u;
            u.x = sspf(s.x + b_r1[cq]);     u.y = sspf(s.y + b_r1[cq + 1]);
            u.z = sspf(s.z + b_r1[cq + 2]); u.w = sspf(s.w + b_r1[cq + 3]);
            st_bf4(&Ms[(hh * 64 + r) * 136 + cq], u);
        }
        __syncthreads();
    }

    // ---- stage 2: W = f@Wlin + U@Wr2; m epilogue -> Ms ----
    acc_zero(acc);
    load_weight512(Bs, g_Wall + OFF_WLIN, 64, tid);
    __syncthreads();
    mma_panel_h(Fs, 72, Bs, 136, acc, wr, wc, 4);
    __syncthreads();
    load_weight512(Bs, g_Wall + OFF_WR2, 64, tid);
    __syncthreads();
    mma_panel_h(Ms, 136, Bs, 136, acc, wr, wc, 4);
    __syncthreads();
    load_weight512(Bs, g_Wall + OFF_WR2 + 64 * 128, 64, tid);
    __syncthreads();
    mma_panel_h(Ms + 64, 136, Bs, 136, acc, wr, wc, 4);
    __syncthreads();
#pragma unroll
    for (int hh = 0; hh < 2; ++hh) {
        if ((wr >> 1) == hh) acc_store_half(S, acc, wr & 1, wc);
        __syncthreads();
#pragma unroll
        for (int p = 0; p < 4; ++p) {
            int idx = tid + p * 512;
            int r = idx >> 5, cq = (idx & 31) * 4;
            int R = hh * 64 + r;
            float4 s = *(const float4*)&S[r * 132 + cq];
            uint2 hr = *(const uint2*)(g_hh + (size_t)srcs[R] * 128 + cq);
            float2 h0 = __bfloat1622float2(*(__nv_bfloat162*)&hr.x);
            float2 h1 = __bfloat1622float2(*(__nv_bfloat162*)&hr.y);
            float ce = Ce[R];
            float4 m;
            m.x = h0.x * (s.x + b_lin[cq]     + b_r2[cq])     * ce;
            m.y = h0.y * (s.y + b_lin[cq + 1] + b_r2[cq + 1]) * ce;
            m.z = h1.x * (s.z + b_lin[cq + 2] + b_r2[cq + 2]) * ce;
            m.w = h1.y * (s.w + b_lin[cq + 3] + b_r2[cq + 3]) * ce;
            st_bf4(&Ms[R * 136 + cq], m);
        }
        __syncthreads();
    }

    // ---- k stage: k = m@Wk, scores epilogue ----
    acc_zero(acc);
    load_weight512(Bs, g_Wall + OFF_WK, 64, tid);
    __syncthreads();
    mma_panel_h(Ms, 136, Bs, 136, acc, wr, wc, 4);
    __syncthreads();
    load_weight512(Bs, g_Wall + OFF_WK + 64 * 128, 64, tid);
    __syncthreads();
    mma_panel_h(Ms + 64, 136, Bs, 136, acc, wr, wc, 4);
    __syncthreads();
#pragma unroll
    for (int hh = 0; hh < 2; ++hh) {
        if ((wr >> 1) == hh) acc_store_half(S, acc, wr & 1, wc);
        __syncthreads();
        {
            int t = tid;          // 512 items: 64 rows x 8 heads
            int r = t >> 3, h = t & 7;
            int R = hh * 64 + r;
            int d = dsts[R];
            const float* kp = &S[r * 132 + h * 16];
            const float4* qp = (const float4*)(g_q + (size_t)d * 128 + h * 16);
            const float* bb = bk + h * 16;
            float s = 0.f;
#pragma unroll
            for (int i = 0; i < 4; ++i) {
                float4 qv = qp[i];
                s += (kp[i * 4 + 0] + bb[i * 4 + 0]) * qv.x;
                s += (kp[i * 4 + 1] + bb[i * 4 + 1]) * qv.y;
                s += (kp[i * 4 + 2] + bb[i * 4 + 2]) * qv.z;
                s += (kp[i * 4 + 3] + bb[i * 4 + 3]) * qv.w;
            }
            s *= 0.25f;
            g_sc[(size_t)(rowBase + R) * NH + h] = s;
            atomicMax(&g_smax[d * NH + h], fenc(s));
        }
        __syncthreads();
    }

    // ---- v stage: v = m@Wv + bv -> g_vh ----
    acc_zero(acc);
    load_weight512(Bs, g_Wall + OFF_WV, 64, tid);
    __syncthreads();
    mma_panel_h(Ms, 136, Bs, 136, acc, wr, wc, 4);
    __syncthreads();
    load_weight512(Bs, g_Wall + OFF_WV + 64 * 128, 64, tid);
    __syncthreads();
    mma_panel_h(Ms + 64, 136, Bs, 136, acc, wr, wc, 4);
    __syncthreads();
#pragma unroll
    for (int hh = 0; hh < 2; ++hh) {
        if ((wr >> 1) == hh) acc_store_half(S, acc, wr & 1, wc);
        __syncthreads();
#pragma unroll
        for (int p = 0; p < 4; ++p) {
            int idx = tid + p * 512;
            int r = idx >> 5, cq = (idx & 31) * 4;
            float4 s = *(const float4*)&S[r * 132 + cq];
            s.x += bv[cq]; s.y += bv[cq + 1]; s.z += bv[cq + 2]; s.w += bv[cq + 3];
            st_bf4(&g_vh[(size_t)(rowBase + hh * 64 + r) * 128 + cq], s);
        }
        __syncthreads();
    }
}

// ---------------- gather aggregation: one warp per node ------------------------
__global__ __launch_bounds__(256)
void agg_kernel() {
    int w = (blockIdx.x * blockDim.x + threadIdx.x) >> 5;
    if (w >= NNODE) return;
    int l = threadIdx.x & 31;
    int c4 = l * 4;
    int h = l >> 2;
    float smax = fdec(g_smax[w * NH + h]);
    int o0 = g_off[w], o1 = g_off[w + 1];
    float a0 = 0.f, a1 = 0.f, a2 = 0.f, a3 = 0.f, den = 0.f;
    for (int i = o0; i < o1; ++i) {
        int e = g_eid[i];
        float ex = expf(g_sc[(size_t)e * NH + h] - smax);
        den += ex;
        uint2 raw = *(const uint2*)(g_vh + (size_t)e * 128 + c4);
        float2 v0 = __bfloat1622float2(*(__nv_bfloat162*)&raw.x);
        float2 v1 = __bfloat1622float2(*(__nv_bfloat162*)&raw.y);
        a0 += ex * v0.x; a1 += ex * v0.y; a2 += ex * v1.x; a3 += ex * v1.y;
    }
    float inv = 1.f / (den + 1e-16f);
    float4 o = make_float4(a0 * inv, a1 * inv, a2 * inv, a3 * inv);
    *(float4*)(g_agg + (size_t)w * 128 + c4) = o;
}

// ---------------- launch --------------------------------------------------------
extern "C" void kernel_launch(void* const* d_in, const int* in_sizes, int n_in,
                              void* d_out, int out_size) {
    const float* x     = (const float*)d_in[0];
    const float* t     = (const float*)d_in[1];
    const float* f_ij  = (const float*)d_in[2];
    const float* r_ij  = (const float*)d_in[3];
    const int*   src   = (const int*)d_in[4];
    const int*   dst   = (const int*)d_in[5];
    const float* W_lin = (const float*)d_in[6];
    const float* b_lin = (const float*)d_in[7];
    const float* W_r1  = (const float*)d_in[8];
    const float* b_r1  = (const float*)d_in[9];
    const float* W_r2  = (const float*)d_in[10];
    const float* b_r2  = (const float*)d_in[11];
    const float* Wq    = (const float*)d_in[12];
    const float* bq    = (const float*)d_in[13];
    const float* Wk    = (const float*)d_in[14];
    const float* bk    = (const float*)d_in[15];
    const float* Wv    = (const float*)d_in[16];
    const float* bv    = (const float*)d_in[17];
    const float* Wo    = (const float*)d_in[18];
    const float* bo    = (const float*)d_in[19];
    const float* ln_g  = (const float*)d_in[20];
    const float* ln_b  = (const float*)d_in[21];
    float* out = (float*)d_out;

    bf16 *pWall, *phh;
    float *pq, *pagg;
    cudaGetSymbolAddress((void**)&pWall, g_Wall);
    cudaGetSymbolAddress((void**)&phh, g_hh);
    cudaGetSymbolAddress((void**)&pq,  g_q);
    cudaGetSymbolAddress((void**)&pagg, g_agg);

    const int SM_NODE = 128 * 132 * 4 + 2 * (128 * 136 * 2);
    cudaFuncSetAttribute((const void*)node_gemm_h<0, true>,  cudaFuncAttributeMaxDynamicSharedMemorySize, SM_NODE);
    cudaFuncSetAttribute((const void*)node_gemm_h<3, false>, cudaFuncAttributeMaxDynamicSharedMemorySize, SM_NODE);
    cudaFuncSetAttribute((const void*)edge_fused_kernel,     cudaFuncAttributeMaxDynamicSharedMemorySize, SMO_TOT);

    const int TB = 256;
    int gridN  = (NNODE * Dm + TB - 1) / TB;
    int gridE  = (NEDGE + TB - 1) / TB;
    int gemmE  = NEDGE / 128;           // 5000
    int gemmN  = (NNODE + 127) / 128;   // 313

    convert_all_kernel<<<W_TOTAL / 512, 512>>>(W_r1, W_lin, W_r2, Wq, Wk, Wv, Wo); // 0
    init_kernel<<<gridN, TB>>>();                                                   // 1
    add_h_kernel<<<gridN, TB>>>(x, t);                                              // 2
    node_gemm_h<0, true><<<gemmN, 512, SM_NODE>>>(phh, pWall + OFF_WQ, bq, pq,      // 3
                                                  NNODE, nullptr, nullptr, nullptr);
    hist_kernel<<<gridE, TB>>>(dst);                                                // 4
    edge_fused_kernel<<<gemmE, 512, SMO_TOT>>>(f_ij, r_ij, src, dst,                // 5
                                               b_r1, b_lin, b_r2, bk, bv);
    scan_kernel<<<1, 1024>>>();                                                     // 6
    idscatter_kernel<<<gridE, TB>>>(dst);                                           // 7
    agg_kernel<<<(NNODE * 32 + TB - 1) / TB, TB>>>();                               // 8
    node_gemm_h<3, false><<<gemmN, 512, SM_NODE>>>(pagg, pWall + OFF_WO, bo, out,   // 9
                                                   NNODE, x, ln_g, ln_b);
}

// round 8
// speedup vs baseline: 3.0421x; 1.0617x over previous
#include <cuda_runtime.h>
#include <cuda_bf16.h>
#include <mma.h>
using namespace nvcuda;
typedef __nv_bfloat16 bf16;

#define Dm 128
#define NH 8
#define NNODE 40000
#define NEDGE 640000

// ---------------- scratch (static device globals) -----------------------------
__device__ bf16  g_hh[(size_t)NNODE * Dm];     // h = x+t, bf16
__device__ float g_q[(size_t)NNODE * Dm];      // queries fp32
__device__ bf16  g_vh[(size_t)NEDGE * Dm];     // values bf16
__device__ float g_sc[(size_t)NEDGE * NH];     // raw scores
__device__ unsigned g_smax[(size_t)NNODE * NH];
__device__ float g_agg[(size_t)NNODE * Dm];
// CSR build
__device__ int g_cnt[NNODE];
__device__ int g_cur[NNODE];
__device__ int g_off[NNODE + 1];
__device__ int g_eid[NEDGE];
// all bf16 weights in one buffer
#define OFF_WR1  0
#define OFF_WLIN 8192
#define OFF_WR2  16384
#define OFF_WQ   32768
#define OFF_WK   49152
#define OFF_WV   65536
#define OFF_WO   81920
#define W_TOTAL  98304
__device__ bf16 g_Wall[W_TOTAL];

// ---------------- helpers ------------------------------------------------------
__device__ __forceinline__ unsigned fenc(float f) {
    unsigned u = __float_as_uint(f);
    return (u & 0x80000000u) ? ~u : (u | 0x80000000u);
}
__device__ __forceinline__ float fdec(unsigned u) {
    return __uint_as_float((u & 0x80000000u) ? (u ^ 0x80000000u) : ~u);
}
#define SMAX_INIT 0x007fffffu

// branch-free shifted softplus: ln2*log2(1+2^(v/ln2)) - ln2
__device__ __forceinline__ float sspf(float v) {
    float t, l;
    asm("ex2.approx.f32 %0, %1;" : "=f"(t) : "f"(v * 1.4426950408889634f));
    asm("lg2.approx.f32 %0, %1;" : "=f"(l) : "f"(1.0f + t));
    return fmaf(0.6931471805599453f, l, -0.6931471805599453f);
}
__device__ __forceinline__ float cutoff(float r) {
    float c = 0.5f * (cosf(r * 0.39269908169872414f) + 1.f);
    return (r < 8.f) ? c : 0.f;
}
__device__ __forceinline__ void st_bf4(bf16* p, float4 v) {
    __nv_bfloat162 a = __floats2bfloat162_rn(v.x, v.y);
    __nv_bfloat162 b = __floats2bfloat162_rn(v.z, v.w);
    uint2 u; u.x = *(unsigned*)&a; u.y = *(unsigned*)&b;
    *(uint2*)p = u;
}

// ---------------- small kernels ------------------------------------------------
__global__ void convert_all_kernel(const float* __restrict__ a0, const float* __restrict__ a1,
                                   const float* __restrict__ a2, const float* __restrict__ a3,
                                   const float* __restrict__ a4, const float* __restrict__ a5,
                                   const float* __restrict__ a6) {
    int i = blockIdx.x * blockDim.x + threadIdx.x;
    if (i >= W_TOTAL) return;
    const float* s; int rel;
    if      (i < 8192)  { s = a0; rel = i; }
    else if (i < 16384) { s = a1; rel = i - 8192; }
    else if (i < 32768) { s = a2; rel = i - 16384; }
    else if (i < 49152) { s = a3; rel = i - 32768; }
    else if (i < 65536) { s = a4; rel = i - 49152; }
    else if (i < 81920) { s = a5; rel = i - 65536; }
    else                { s = a6; rel = i - 81920; }
    g_Wall[i] = __float2bfloat16(s[rel]);
}
__global__ void init_smax_kernel() {
    int gid = blockIdx.x * blockDim.x + threadIdx.x;
    if (gid < NNODE * NH) g_smax[gid] = SMAX_INIT;
}
__global__ void init_csr_kernel() {
    int gid = blockIdx.x * blockDim.x + threadIdx.x;
    if (gid < NNODE) { g_cnt[gid] = 0; g_cur[gid] = 0; }
}
__global__ void add_h_kernel(const float* __restrict__ x, const float* __restrict__ t) {
    int gid = blockIdx.x * blockDim.x + threadIdx.x;
    if (gid < NNODE * Dm) g_hh[gid] = __float2bfloat16(x[gid] + t[gid]);
}

// ---------------- CSR build ----------------------------------------------------
__global__ void hist_kernel(const int* __restrict__ dst) {
    int e = blockIdx.x * blockDim.x + threadIdx.x;
    if (e < NEDGE) atomicAdd(&g_cnt[dst[e]], 1);
}
__global__ __launch_bounds__(1024) void scan_kernel() {
    __shared__ int part[1024];
    const int C = (NNODE + 1023) / 1024;
    int t = threadIdx.x;
    int base = t * C;
    int s = 0;
    for (int i = 0; i < C; ++i) {
        int idx = base + i;
        if (idx < NNODE) s += g_cnt[idx];
    }
    part[t] = s;
    __syncthreads();
    for (int d = 1; d < 1024; d <<= 1) {
        int v = (t >= d) ? part[t - d] : 0;
        __syncthreads();
        part[t] += v;
        __syncthreads();
    }
    int run = part[t] - s;
    for (int i = 0; i < C; ++i) {
        int idx = base + i;
        if (idx < NNODE) { g_off[idx] = run; run += g_cnt[idx]; }
    }
    if (t == 1023) g_off[NNODE] = run;
}
__global__ void idscatter_kernel(const int* __restrict__ dst) {
    int e = blockIdx.x * blockDim.x + threadIdx.x;
    if (e < NEDGE) {
        int d = dst[e];
        int p = g_off[d] + atomicAdd(&g_cur[d], 1);
        g_eid[p] = e;
    }
}

// ---------------- wmma bf16 machinery ------------------------------------------
typedef wmma::fragment<wmma::matrix_a, 16, 16, 16, bf16, wmma::row_major> HA;
typedef wmma::fragment<wmma::matrix_b, 16, 16, 16, bf16, wmma::row_major> HB;
typedef wmma::fragment<wmma::accumulator, 16, 16, 16, float> HC;

__device__ __forceinline__ void mma_panel_h(const bf16* As, int lda,
                                            const bf16* Bs, int ldb,
                                            HC (&acc)[2][2], int wr, int wc, int ksteps) {
    for (int kk = 0; kk < ksteps; ++kk) {
        HA a[2]; HB b[2];
#pragma unroll
        for (int i = 0; i < 2; ++i)
            wmma::load_matrix_sync(a[i], As + (size_t)(wr * 32 + i * 16) * lda + kk * 16, lda);
#pragma unroll
        for (int j = 0; j < 2; ++j)
            wmma::load_matrix_sync(b[j], Bs + (size_t)(kk * 16) * ldb + wc * 32 + j * 16, ldb);
#pragma unroll
        for (int i = 0; i < 2; ++i)
#pragma unroll
            for (int j = 0; j < 2; ++j) wmma::mma_sync(acc[i][j], a[i], b[j], acc[i][j]);
    }
}
__device__ __forceinline__ void acc_zero(HC (&acc)[2][2]) {
#pragma unroll
    for (int i = 0; i < 2; ++i)
#pragma unroll
        for (int j = 0; j < 2; ++j) wmma::fill_fragment(acc[i][j], 0.f);
}
__device__ __forceinline__ void acc_store(float* S, HC (&acc)[2][2], int wr, int wc) {
#pragma unroll
    for (int i = 0; i < 2; ++i)
#pragma unroll
        for (int j = 0; j < 2; ++j)
            wmma::store_matrix_sync(S + (size_t)(wr * 32 + i * 16) * 132 + wc * 32 + j * 16,
                                    acc[i][j], 132, wmma::mem_row_major);
}
__device__ __forceinline__ void acc_store_half(float* S, HC (&acc)[2][2], int wrl, int wc) {
#pragma unroll
    for (int i = 0; i < 2; ++i)
#pragma unroll
        for (int j = 0; j < 2; ++j)
            wmma::store_matrix_sync(S + (size_t)(wrl * 32 + i * 16) * 132 + wc * 32 + j * 16,
                                    acc[i][j], 132, wmma::mem_row_major);
}
__device__ __forceinline__ void load_weight512(bf16* Bs, const bf16* W, int rows, int tid) {
    int n = rows * 16;
    for (int idx = tid; idx < n; idx += 512) {
        int r = idx >> 4, c8 = (idx & 15) * 8;
        *(uint4*)&Bs[r * 136 + c8] = *(const uint4*)(W + (size_t)r * 128 + c8);
    }
}
// 64-row panel = 1024 uint4 = exactly 2 per thread (512 threads)
__device__ __forceinline__ void ldg_panel(uint4& w0, uint4& w1, const bf16* W, int tid) {
    const uint4* p = (const uint4*)W;
    w0 = p[tid]; w1 = p[tid + 512];
}
__device__ __forceinline__ void sts_panel(bf16* Bs, uint4 w0, uint4 w1, int tid) {
    int r0 = tid >> 4, c0 = (tid & 15) * 8;
    *(uint4*)&Bs[r0 * 136 + c0] = w0;
    int t1 = tid + 512;
    int r1 = t1 >> 4, c1 = (t1 & 15) * 8;
    *(uint4*)&Bs[r1 * 136 + c1] = w1;
}

// ---------------- node GEMM: MODE 0 = +bias; MODE 3 = resid+LN -----------------
template <int MODE, bool AB16>
__global__ __launch_bounds__(512)
void node_gemm_h(const void* __restrict__ Ain, const bf16* __restrict__ W,
                 const float* __restrict__ bias, float* __restrict__ C, int M,
                 const float* __restrict__ resid,
                 const float* __restrict__ ln_g, const float* __restrict__ ln_b)
{
    extern __shared__ char smraw[];
    float* S  = (float*)smraw;                        // 128*132 f32
    bf16*  As = (bf16*)(smraw + 128 * 132 * 4);       // 128*136
    bf16*  Bs = As + 128 * 136;                       // 128*136
    const int tid = threadIdx.x, wid = tid >> 5;
    const int wr = wid >> 2, wc = wid & 3;
    const int rowBase = blockIdx.x * 128;

    if constexpr (AB16) {
        const bf16* A = (const bf16*)Ain;
#pragma unroll
        for (int p = 0; p < 4; ++p) {
            int idx = tid + p * 512;
            int r = idx >> 4, c8 = (idx & 15) * 8;
            int gr = rowBase + r;
            uint4 v = make_uint4(0, 0, 0, 0);
            if (gr < M) v = *(const uint4*)(A + (size_t)gr * 128 + c8);
            *(uint4*)&As[r * 136 + c8] = v;
        }
    } else {
        const float* A = (const float*)Ain;
#pragma unroll
        for (int p = 0; p < 8; ++p) {
            int idx = tid + p * 512;
            int r = idx >> 5, cg = (idx & 31) * 4;
            int gr = rowBase + r;
            float4 v = make_float4(0.f, 0.f, 0.f, 0.f);
            if (gr < M) v = *(const float4*)(A + (size_t)gr * 128 + cg);
            st_bf4(&As[r * 136 + cg], v);
        }
    }
    load_weight512(Bs, W, 128, tid);
    __syncthreads();

    HC acc[2][2];
    acc_zero(acc);
    mma_panel_h(As, 136, Bs, 136, acc, wr, wc, 8);
    __syncthreads();
    acc_store(S, acc, wr, wc);
    __syncthreads();

    if constexpr (MODE == 0) {
        for (int idx = tid; idx < 4096; idx += 512) {
            int r = idx >> 5, cq = (idx & 31) * 4;
            int gr = rowBase + r;
            if (gr < M) {
                float4 s = *(const float4*)&S[r * 132 + cq];
                s.x += bias[cq]; s.y += bias[cq + 1]; s.z += bias[cq + 2]; s.w += bias[cq + 3];
                *(float4*)(C + (size_t)gr * 128 + cq) = s;
            }
        }
    } else {
        __shared__ float muS[128], invS[128];
        for (int idx = tid; idx < 4096; idx += 512) {
            int r = idx >> 5, cq = (idx & 31) * 4;
            int gr = rowBase + r;
            if (gr < M) {
                float4 s = *(const float4*)&S[r * 132 + cq];
                float4 rr = *(const float4*)(resid + (size_t)gr * 128 + cq);
                s.x += bias[cq] + rr.x;     s.y += bias[cq + 1] + rr.y;
                s.z += bias[cq + 2] + rr.z; s.w += bias[cq + 3] + rr.w;
                *(float4*)&S[r * 132 + cq] = s;
            }
        }
        __syncthreads();
        if (tid < 128) {
            int gr = rowBase + tid;
            if (gr < M) {
                float s = 0.f, q2 = 0.f;
#pragma unroll 4
                for (int c = 0; c < 128; ++c) { float v = S[tid * 132 + c]; s += v; q2 += v * v; }
                float mean = s * (1.f / 128.f);
                float var = q2 * (1.f / 128.f) - mean * mean;
                muS[tid] = mean; invS[tid] = rsqrtf(var + 1e-5f);
            }
        }
        __syncthreads();
        for (int idx = tid; idx < 4096; idx += 512) {
            int r = idx >> 5, cq = (idx & 31) * 4;
            int gr = rowBase + r;
            if (gr < M) {
                float4 s = *(const float4*)&S[r * 132 + cq];
                float4 o;
                o.x = (s.x - muS[r]) * invS[r] * ln_g[cq]     + ln_b[cq];
                o.y = (s.y - muS[r]) * invS[r] * ln_g[cq + 1] + ln_b[cq + 1];
                o.z = (s.z - muS[r]) * invS[r] * ln_g[cq + 2] + ln_b[cq + 2];
                o.w = (s.w - muS[r]) * invS[r] * ln_g[cq + 3] + ln_b[cq + 3];
                *(float4*)(C + (size_t)gr * 128 + cq) = o;
            }
        }
    }
}

// ---------------- mega edge kernel (BM=128, 512 thr, 2 CTAs/SM) ----------------
// weight panels prefetched into registers one step ahead (hides L2 latency)
#define SMO_S 0
#define SMO_F 33792
#define SMO_M 52224
#define SMO_B 87040
#define SMO_TOT 104448
__global__ __launch_bounds__(512, 2)
void edge_fused_kernel(const float* __restrict__ f_ij, const float* __restrict__ r_ij,
                       const int* __restrict__ src, const int* __restrict__ dst,
                       const float* __restrict__ b_r1, const float* __restrict__ b_lin,
                       const float* __restrict__ b_r2,
                       const float* __restrict__ bk, const float* __restrict__ bv)
{
    extern __shared__ char smraw[];
    float* S  = (float*)(smraw + SMO_S);     // 64*132 f32 (half staging)
    bf16*  Fs = (bf16*)(smraw + SMO_F);      // 128*72
    bf16*  Ms = (bf16*)(smraw + SMO_M);      // 128*136
    bf16*  Bs = (bf16*)(smraw + SMO_B);      // 64*136 (one weight panel)
    __shared__ float Ce[128];
    __shared__ int   srcs[128], dsts[128];

    const int tid = threadIdx.x, wid = tid >> 5;
    const int wr = wid >> 2, wc = wid & 3;          // 4x4 warp grid
    const int rowBase = blockIdx.x * 128;           // NEDGE = 5000*128 exactly

    uint4 w0, w1;
    // P0 = Wr1 prefetch
    ldg_panel(w0, w1, g_Wall + OFF_WR1, tid);

    // f tile: 128 x 64 fp32 -> bf16 (2048 float4)
#pragma unroll
    for (int p = 0; p < 4; ++p) {
        int idx = tid + p * 512;
        int r = idx >> 4, cg = (idx & 15) * 4;
        float4 v = *(const float4*)(f_ij + (size_t)(rowBase + r) * 64 + cg);
        st_bf4(&Fs[r * 72 + cg], v);
    }
    if (tid < 128) {
        int e = rowBase + tid;
        Ce[tid] = cutoff(r_ij[e]);
        srcs[tid] = src[e];
        dsts[tid] = dst[e];
    }
    sts_panel(Bs, w0, w1, tid);                     // P0 (Bs has no prior readers)
    ldg_panel(w0, w1, g_Wall + OFF_WLIN, tid);      // P1
    __syncthreads();

    HC acc[2][2];

    // ---- stage 1: U = ssp(f @ Wr1 + br1) -> Ms ----
    acc_zero(acc);
    mma_panel_h(Fs, 72, Bs, 136, acc, wr, wc, 4);
    __syncthreads();
    sts_panel(Bs, w0, w1, tid);                     // P1 = Wlin
    ldg_panel(w0, w1, g_Wall + OFF_WR2, tid);       // P2
#pragma unroll
    for (int hh = 0; hh < 2; ++hh) {
        if ((wr >> 1) == hh) acc_store_half(S, acc, wr & 1, wc);
        __syncthreads();
#pragma unroll
        for (int p = 0; p < 4; ++p) {
            int idx = tid + p * 512;
            int r = idx >> 5, cq = (idx & 31) * 4;
            float4 s = *(const float4*)&S[r * 132 + cq];
            float4 u;
            u.x = sspf(s.x + b_r1[cq]);     u.y = sspf(s.y + b_r1[cq + 1]);
            u.z = sspf(s.z + b_r1[cq + 2]); u.w = sspf(s.w + b_r1[cq + 3]);
            st_bf4(&Ms[(hh * 64 + r) * 136 + cq], u);
        }
        __syncthreads();
    }

    // ---- stage 2: W = f@Wlin + U@Wr2 ----
    acc_zero(acc);
    mma_panel_h(Fs, 72, Bs, 136, acc, wr, wc, 4);   // f@Wlin
    __syncthreads();
    sts_panel(Bs, w0, w1, tid);                     // P2 = Wr2 lo
    ldg_panel(w0, w1, g_Wall + OFF_WR2 + 64 * 128, tid);  // P3
    __syncthreads();
    mma_panel_h(Ms, 136, Bs, 136, acc, wr, wc, 4);  // U[:,0:64)@Wr2lo
    __syncthreads();
    sts_panel(Bs, w0, w1, tid);                     // P3 = Wr2 hi
    ldg_panel(w0, w1, g_Wall + OFF_WK, tid);        // P4
    __syncthreads();
    mma_panel_h(Ms + 64, 136, Bs, 136, acc, wr, wc, 4);
    __syncthreads();
    sts_panel(Bs, w0, w1, tid);                     // P4 = Wk lo
    ldg_panel(w0, w1, g_Wall + OFF_WK + 64 * 128, tid);   // P5
    // m epilogue -> Ms = m (loop syncs make Bs(P4) visible after)
#pragma unroll
    for (int hh = 0; hh < 2; ++hh) {
        if ((wr >> 1) == hh) acc_store_half(S, acc, wr & 1, wc);
        __syncthreads();
#pragma unroll
        for (int p = 0; p < 4; ++p) {
            int idx = tid + p * 512;
            int r = idx >> 5, cq = (idx & 31) * 4;
            int R = hh * 64 + r;
            float4 s = *(const float4*)&S[r * 132 + cq];
            uint2 hr = *(const uint2*)(g_hh + (size_t)srcs[R] * 128 + cq);
            float2 h0 = __bfloat1622float2(*(__nv_bfloat162*)&hr.x);
            float2 h1 = __bfloat1622float2(*(__nv_bfloat162*)&hr.y);
            float ce = Ce[R];
            float4 m;
            m.x = h0.x * (s.x + b_lin[cq]     + b_r2[cq])     * ce;
            m.y = h0.y * (s.y + b_lin[cq + 1] + b_r2[cq + 1]) * ce;
            m.z = h1.x * (s.z + b_lin[cq + 2] + b_r2[cq + 2]) * ce;
            m.w = h1.y * (s.w + b_lin[cq + 3] + b_r2[cq + 3]) * ce;
            st_bf4(&Ms[R * 136 + cq], m);
        }
        __syncthreads();
    }

    // ---- k stage: k = m@Wk, scores epilogue ----
    acc_zero(acc);
    mma_panel_h(Ms, 136, Bs, 136, acc, wr, wc, 4);  // m lo K @ Wk lo
    __syncthreads();
    sts_panel(Bs, w0, w1, tid);                     // P5 = Wk hi
    ldg_panel(w0, w1, g_Wall + OFF_WV, tid);        // P6
    __syncthreads();
    mma_panel_h(Ms + 64, 136, Bs, 136, acc, wr, wc, 4);
    __syncthreads();
    sts_panel(Bs, w0, w1, tid);                     // P6 = Wv lo
    ldg_panel(w0, w1, g_Wall + OFF_WV + 64 * 128, tid);   // P7
    // score epilogue (loop syncs make Bs(P6) visible after)
#pragma unroll
    for (int hh = 0; hh < 2; ++hh) {
        if ((wr >> 1) == hh) acc_store_half(S, acc, wr & 1, wc);
        __syncthreads();
        {
            int r = tid >> 3, h = tid & 7;          // 512 items: 64 rows x 8 heads
            int R = hh * 64 + r;
            int d = dsts[R];
            const float* kp = &S[r * 132 + h * 16];
            const float4* qp = (const float4*)(g_q + (size_t)d * 128 + h * 16);
            const float* bb = bk + h * 16;
            float s = 0.f;
#pragma unroll
            for (int i = 0; i < 4; ++i) {
                float4 qv = qp[i];
                s += (kp[i * 4 + 0] + bb[i * 4 + 0]) * qv.x;
                s += (kp[i * 4 + 1] + bb[i * 4 + 1]) * qv.y;
                s += (kp[i * 4 + 2] + bb[i * 4 + 2]) * qv.z;
                s += (kp[i * 4 + 3] + bb[i * 4 + 3]) * qv.w;
            }
            s *= 0.25f;
            g_sc[(size_t)(rowBase + R) * NH + h] = s;
            atomicMax(&g_smax[d * NH + h], fenc(s));
        }
        __syncthreads();
    }

    // ---- v stage: v = m@Wv + bv -> g_vh ----
    acc_zero(acc);
    mma_panel_h(Ms, 136, Bs, 136, acc, wr, wc, 4);  // m lo K @ Wv lo
    __syncthreads();
    sts_panel(Bs, w0, w1, tid);                     // P7 = Wv hi
    __syncthreads();
    mma_panel_h(Ms + 64, 136, Bs, 136, acc, wr, wc, 4);
    __syncthreads();
#pragma unroll
    for (int hh = 0; hh < 2; ++hh) {
        if ((wr >> 1) == hh) acc_store_half(S, acc, wr & 1, wc);
        __syncthreads();
#pragma unroll
        for (int p = 0; p < 4; ++p) {
            int idx = tid + p * 512;
            int r = idx >> 5, cq = (idx & 31) * 4;
            float4 s = *(const float4*)&S[r * 132 + cq];
            s.x += bv[cq]; s.y += bv[cq + 1]; s.z += bv[cq + 2]; s.w += bv[cq + 3];
            st_bf4(&g_vh[(size_t)(rowBase + hh * 64 + r) * 128 + cq], s);
        }
        __syncthreads();
    }
}

// ---------------- gather aggregation: one warp per node ------------------------
__global__ __launch_bounds__(256)
void agg_kernel() {
    int w = (blockIdx.x * blockDim.x + threadIdx.x) >> 5;
    if (w >= NNODE) return;
    int l = threadIdx.x & 31;
    int c4 = l * 4;
    int h = l >> 2;
    float smax = fdec(g_smax[w * NH + h]);
    int o0 = g_off[w], o1 = g_off[w + 1];
    float a0 = 0.f, a1 = 0.f, a2 = 0.f, a3 = 0.f, den = 0.f;
    for (int i = o0; i < o1; ++i) {
        int e = g_eid[i];
        float ex = expf(g_sc[(size_t)e * NH + h] - smax);
        den += ex;
        uint2 raw = *(const uint2*)(g_vh + (size_t)e * 128 + c4);
        float2 v0 = __bfloat1622float2(*(__nv_bfloat162*)&raw.x);
        float2 v1 = __bfloat1622float2(*(__nv_bfloat162*)&raw.y);
        a0 += ex * v0.x; a1 += ex * v0.y; a2 += ex * v1.x; a3 += ex * v1.y;
    }
    float inv = 1.f / (den + 1e-16f);
    float4 o = make_float4(a0 * inv, a1 * inv, a2 * inv, a3 * inv);
    *(float4*)(g_agg + (size_t)w * 128 + c4) = o;
}

// ---------------- launch --------------------------------------------------------
extern "C" void kernel_launch(void* const* d_in, const int* in_sizes, int n_in,
                              void* d_out, int out_size) {
    const float* x     = (const float*)d_in[0];
    const float* t     = (const float*)d_in[1];
    const float* f_ij  = (const float*)d_in[2];
    const float* r_ij  = (const float*)d_in[3];
    const int*   src   = (const int*)d_in[4];
    const int*   dst   = (const int*)d_in[5];
    const float* W_lin = (const float*)d_in[6];
    const float* b_lin = (const float*)d_in[7];
    const float* W_r1  = (const float*)d_in[8];
    const float* b_r1  = (const float*)d_in[9];
    const float* W_r2  = (const float*)d_in[10];
    const float* b_r2  = (const float*)d_in[11];
    const float* Wq    = (const float*)d_in[12];
    const float* bq    = (const float*)d_in[13];
    const float* Wk    = (const float*)d_in[14];
    const float* bk    = (const float*)d_in[15];
    const float* Wv    = (const float*)d_in[16];
    const float* bv    = (const float*)d_in[17];
    const float* Wo    = (const float*)d_in[18];
    const float* bo    = (const float*)d_in[19];
    const float* ln_g  = (const float*)d_in[20];
    const float* ln_b  = (const float*)d_in[21];
    float* out = (float*)d_out;

    bf16 *pWall, *phh;
    float *pq, *pagg;
    cudaGetSymbolAddress((void**)&pWall, g_Wall);
    cudaGetSymbolAddress((void**)&phh, g_hh);
    cudaGetSymbolAddress((void**)&pq,  g_q);
    cudaGetSymbolAddress((void**)&pagg, g_agg);

    // side stream + events (created once, on the non-captured correctness call)
    static cudaStream_t s_side = nullptr;
    static cudaEvent_t ev_fork = nullptr, ev_join = nullptr;
    if (s_side == nullptr) {
        cudaStreamCreateWithFlags(&s_side, cudaStreamNonBlocking);
        cudaEventCreateWithFlags(&ev_fork, cudaEventDisableTiming);
        cudaEventCreateWithFlags(&ev_join, cudaEventDisableTiming);
    }

    const int SM_NODE = 128 * 132 * 4 + 2 * (128 * 136 * 2);
    cudaFuncSetAttribute((const void*)node_gemm_h<0, true>,  cudaFuncAttributeMaxDynamicSharedMemorySize, SM_NODE);
    cudaFuncSetAttribute((const void*)node_gemm_h<3, false>, cudaFuncAttributeMaxDynamicSharedMemorySize, SM_NODE);
    cudaFuncSetAttribute((const void*)edge_fused_kernel,     cudaFuncAttributeMaxDynamicSharedMemorySize, SMO_TOT);

    const int TB = 256;
    int gridN  = (NNODE * Dm + TB - 1) / TB;
    int gridE  = (NEDGE + TB - 1) / TB;
    int gemmE  = NEDGE / 128;           // 5000
    int gemmN  = (NNODE + 127) / 128;   // 313

    // ---- main stream ----
    convert_all_kernel<<<W_TOTAL / 512, 512>>>(W_r1, W_lin, W_r2, Wq, Wk, Wv, Wo);
    add_h_kernel<<<gridN, TB>>>(x, t);

    // ---- fork: CSR build on side stream (independent of GEMM chain) ----
    cudaEventRecord(ev_fork, 0);
    cudaStreamWaitEvent(s_side, ev_fork, 0);
    init_csr_kernel<<<(NNODE + TB - 1) / TB, TB, 0, s_side>>>();
    hist_kernel<<<gridE, TB, 0, s_side>>>(dst);
    scan_kernel<<<1, 1024, 0, s_side>>>();
    idscatter_kernel<<<gridE, TB, 0, s_side>>>(dst);
    cudaEventRecord(ev_join, s_side);

    // ---- main continues ----
    init_smax_kernel<<<(NNODE * NH + TB - 1) / TB, TB>>>();
    node_gemm_h<0, true><<<gemmN, 512, SM_NODE>>>(phh, pWall + OFF_WQ, bq, pq,
                                                  NNODE, nullptr, nullptr, nullptr);
    edge_fused_kernel<<<gemmE, 512, SMO_TOT>>>(f_ij, r_ij, src, dst,
                                               b_r1, b_lin, b_r2, bk, bv);

    // ---- join, then aggregation + output ----
    cudaStreamWaitEvent(0, ev_join, 0);
    agg_kernel<<<(NNODE * 32 + TB - 1) / TB, TB>>>();
    node_gemm_h<3, false><<<gemmN, 512, SM_NODE>>>(pagg, pWall + OFF_WO, bo, out,
                                                   NNODE, x, ln_g, ln_b);
}